// round 5
// baseline (speedup 1.0000x reference)
#include <cuda_runtime.h>

// Shapes (fixed by the problem)
constexpr int BB = 64;    // batch
constexpr int KK = 256;   // feature dim K
constexpr int TT = 64;    // word tokens
constexpr int DFE = 768;  // image channels
constexpr int NN = 1024;  // regions

// Scratch (device globals: allocation-free contract)
__device__ float g_v[BB * KK * NN];   // v  [B,K,N]  64 MB
__device__ float g_s[BB * TT * NN];   // s / alpha (in place) 16 MB
__device__ float g_c[BB * KK * TT];   // c  [B,K,T]  4 MB

typedef unsigned long long u64;

// ---- packed f32x2 helpers (Blackwell FFMA2) -------------------------------
__device__ __forceinline__ u64 bcast2(float x) {
    u64 r;
    asm("mov.b64 %0, {%1, %1};" : "=l"(r) : "f"(x));
    return r;
}
__device__ __forceinline__ void fma2(u64& c, u64 a, u64 b) {
    asm("fma.rn.f32x2 %0, %1, %2, %3;" : "=l"(c) : "l"(a), "l"(b), "l"(c));
}
__device__ __forceinline__ float2 u2f2(u64 v) {
    float2 f;
    asm("mov.b64 {%0, %1}, %2;" : "=f"(f.x), "=f"(f.y) : "l"(v));
    return f;
}

// ---------------------------------------------------------------------------
// TN GEMM: C[m][n] = sum_k A[k*lda + m] * B[k*ldb + n]  (+ bias[m])
// Tile TM x TN, 256 threads (16x16), each thread RM x RN (RN must be 4).
// Inner product uses packed f32x2 FMAs (rows paired).
// ---------------------------------------------------------------------------
template <int TM, int TN_, int RM, int RN, bool BIAS>
__global__ __launch_bounds__(256) void gemm_tn(
    const float* __restrict__ A, const float* __restrict__ B,
    const float* __restrict__ bias, float* __restrict__ C,
    int Ktot, int lda, int ldb, int ldc, long aB, long bB, long cB)
{
    static_assert(RN == 4 && (RM % 4) == 0, "layout");
    constexpr int KC = 16;
    __shared__ float As[KC][TM];
    __shared__ float Bs[KC][TN_];

    const int b  = blockIdx.z;
    const int m0 = blockIdx.y * TM;
    const int n0 = blockIdx.x * TN_;
    const float* Ab = A + (long)b * aB;
    const float* Bb = B + (long)b * bB;
    float* Cb = C + (long)b * cB;

    const int tid = threadIdx.x;
    const int tx = tid & 15, ty = tid >> 4;

    u64 acc[RM / 2][RN];
#pragma unroll
    for (int p = 0; p < RM / 2; p++)
#pragma unroll
        for (int j = 0; j < RN; j++) acc[p][j] = 0ull;

    constexpr int A4 = KC * TM / 4;    // float4 slots in A tile
    constexpr int B4 = KC * TN_ / 4;

    for (int k0 = 0; k0 < Ktot; k0 += KC) {
#pragma unroll
        for (int l = 0; l < A4 / 256; l++) {
            int idx = tid + l * 256;
            int r = idx / (TM / 4), c = idx % (TM / 4);
            *(float4*)&As[r][c * 4] =
                *(const float4*)&Ab[(long)(k0 + r) * lda + m0 + c * 4];
        }
#pragma unroll
        for (int l = 0; l < B4 / 256; l++) {
            int idx = tid + l * 256;
            int r = idx / (TN_ / 4), c = idx % (TN_ / 4);
            *(float4*)&Bs[r][c * 4] =
                *(const float4*)&Bb[(long)(k0 + r) * ldb + n0 + c * 4];
        }
        __syncthreads();

#pragma unroll
        for (int kk = 0; kk < KC; kk++) {
            u64 a2[RM / 2];
#pragma unroll
            for (int q = 0; q < RM / 4; q++) {
                ulonglong2 t = *(const ulonglong2*)&As[kk][ty * RM + q * 4];
                a2[2 * q]     = t.x;
                a2[2 * q + 1] = t.y;
            }
            float4 bvf = *(const float4*)&Bs[kk][tx * RN];
            u64 b2[4] = {bcast2(bvf.x), bcast2(bvf.y), bcast2(bvf.z), bcast2(bvf.w)};
#pragma unroll
            for (int p = 0; p < RM / 2; p++)
#pragma unroll
                for (int j = 0; j < RN; j++) fma2(acc[p][j], a2[p], b2[j]);
        }
        __syncthreads();
    }

#pragma unroll
    for (int p = 0; p < RM / 2; p++) {
        int r0 = m0 + ty * RM + 2 * p;
        float bi0 = 0.f, bi1 = 0.f;
        if (BIAS) { bi0 = bias[r0]; bi1 = bias[r0 + 1]; }
        float2 f0 = u2f2(acc[p][0]);
        float2 f1 = u2f2(acc[p][1]);
        float2 f2 = u2f2(acc[p][2]);
        float2 f3 = u2f2(acc[p][3]);
        float4 o0 = make_float4(f0.x + bi0, f1.x + bi0, f2.x + bi0, f3.x + bi0);
        float4 o1 = make_float4(f0.y + bi1, f1.y + bi1, f2.y + bi1, f3.y + bi1);
        *(float4*)&Cb[(long)r0 * ldc + n0 + tx * RN]       = o0;
        *(float4*)&Cb[(long)(r0 + 1) * ldc + n0 + tx * RN] = o1;
    }
}

// ---------------------------------------------------------------------------
// Row softmax over N=1024 with gamma scaling (in place).  1 block per row.
// ---------------------------------------------------------------------------
__global__ __launch_bounds__(256) void softmax_k(float* __restrict__ S,
                                                 const float* __restrict__ gp)
{
    __shared__ float red[8];
    const long row = blockIdx.x;
    float* s = S + row * NN;
    const int tid = threadIdx.x;
    const float g = *gp;

    float4 v = *(const float4*)&s[tid * 4];
    v.x *= g; v.y *= g; v.z *= g; v.w *= g;

    float m = fmaxf(fmaxf(v.x, v.y), fmaxf(v.z, v.w));
#pragma unroll
    for (int o = 16; o > 0; o >>= 1) m = fmaxf(m, __shfl_xor_sync(0xffffffffu, m, o));
    if ((tid & 31) == 0) red[tid >> 5] = m;
    __syncthreads();
    m = red[0];
#pragma unroll
    for (int i = 1; i < 8; i++) m = fmaxf(m, red[i]);
    __syncthreads();

    float e0 = __expf(v.x - m), e1 = __expf(v.y - m);
    float e2 = __expf(v.z - m), e3 = __expf(v.w - m);
    float sum = (e0 + e1) + (e2 + e3);
#pragma unroll
    for (int o = 16; o > 0; o >>= 1) sum += __shfl_xor_sync(0xffffffffu, sum, o);
    if ((tid & 31) == 0) red[tid >> 5] = sum;
    __syncthreads();
    sum = ((red[0] + red[1]) + (red[2] + red[3])) +
          ((red[4] + red[5]) + (red[6] + red[7]));
    float r = 1.0f / sum;
    float4 o = make_float4(e0 * r, e1 * r, e2 * r, e3 * r);
    *(float4*)&s[tid * 4] = o;
}

// ---------------------------------------------------------------------------
// NT GEMM: c[b][m][t] = sum_n v[b][m][n] * alpha[b][t][n]
// 64(m) x 64(t) tile per block, n in chunks of 16 via smem (padded rows).
// ---------------------------------------------------------------------------
__global__ __launch_bounds__(256) void gemm_nt_c(const float* __restrict__ V,
                                                 const float* __restrict__ Al,
                                                 float* __restrict__ C)
{
    __shared__ float Vs[64][17];
    __shared__ float As[64][17];
    const int b  = blockIdx.z;
    const int m0 = blockIdx.y * 64;
    const float* Vb = V + (long)b * KK * NN + (long)m0 * NN;
    const float* Ab = Al + (long)b * TT * NN;
    const int tid = threadIdx.x;
    const int tx = tid & 15, ty = tid >> 4;
    const int lr = tid >> 2, lc = (tid & 3) * 4;

    float acc[4][4] = {};
    for (int n0 = 0; n0 < NN; n0 += 16) {
        float4 v4 = *(const float4*)&Vb[(long)lr * NN + n0 + lc];
        float4 a4 = *(const float4*)&Ab[(long)lr * NN + n0 + lc];
        Vs[lr][lc] = v4.x; Vs[lr][lc + 1] = v4.y; Vs[lr][lc + 2] = v4.z; Vs[lr][lc + 3] = v4.w;
        As[lr][lc] = a4.x; As[lr][lc + 1] = a4.y; As[lr][lc + 2] = a4.z; As[lr][lc + 3] = a4.w;
        __syncthreads();
#pragma unroll
        for (int nn = 0; nn < 16; nn++) {
            float av[4], bv[4];
#pragma unroll
            for (int i = 0; i < 4; i++) av[i] = Vs[ty * 4 + i][nn];
#pragma unroll
            for (int j = 0; j < 4; j++) bv[j] = As[tx * 4 + j][nn];
#pragma unroll
            for (int i = 0; i < 4; i++)
#pragma unroll
                for (int j = 0; j < 4; j++) acc[i][j] = fmaf(av[i], bv[j], acc[i][j]);
        }
        __syncthreads();
    }
    float* Cb = C + (long)b * KK * TT + (long)m0 * TT;
#pragma unroll
    for (int i = 0; i < 4; i++) {
        float4 o = make_float4(acc[i][0], acc[i][1], acc[i][2], acc[i][3]);
        *(float4*)&Cb[(ty * 4 + i) * TT + tx * 4] = o;
    }
}

// ---------------------------------------------------------------------------
// Finalize: norms + cos[b][i][j] = (sum_k c[k][i] e[k][j]) / (lc[i] le[j])
// One block per batch.
// ---------------------------------------------------------------------------
__global__ __launch_bounds__(256) void finalize_k(const float* __restrict__ Cm,
                                                  const float* __restrict__ E,
                                                  float* __restrict__ Out)
{
    __shared__ float rn[128];          // [0:64) = 1/lc, [64:128) = 1/le
    __shared__ float As[16][64];
    __shared__ float Bs[16][64];
    const int b = blockIdx.x;
    const float* cb = Cm + (long)b * KK * TT;
    const float* eb = E + (long)b * KK * TT;
    const int tid = threadIdx.x;

    if (tid < 128) {
        const float* p = (tid < 64) ? cb : eb;
        int t = tid & 63;
        float ss = 0.f;
        for (int k = 0; k < KK; k++) {
            float x = p[k * TT + t];
            ss = fmaf(x, x, ss);
        }
        rn[tid] = rsqrtf(ss);
    }

    const int tx = tid & 15, ty = tid >> 4;
    float acc[4][4] = {};
    for (int k0 = 0; k0 < KK; k0 += 16) {
        *(float4*)&As[ty][tx * 4] = *(const float4*)&cb[(k0 + ty) * TT + tx * 4];
        *(float4*)&Bs[ty][tx * 4] = *(const float4*)&eb[(k0 + ty) * TT + tx * 4];
        __syncthreads();
#pragma unroll
        for (int kk = 0; kk < 16; kk++) {
            float4 a4 = *(const float4*)&As[kk][ty * 4];
            float4 b4 = *(const float4*)&Bs[kk][tx * 4];
            float av[4] = {a4.x, a4.y, a4.z, a4.w};
            float bv[4] = {b4.x, b4.y, b4.z, b4.w};
#pragma unroll
            for (int i = 0; i < 4; i++)
#pragma unroll
                for (int j = 0; j < 4; j++) acc[i][j] = fmaf(av[i], bv[j], acc[i][j]);
        }
        __syncthreads();
    }

    float* ob = Out + (long)b * TT * TT;
#pragma unroll
    for (int i = 0; i < 4; i++) {
        int ii = ty * 4 + i;
        float ri = rn[ii];
        float4 o;
        o.x = acc[i][0] * ri * rn[64 + tx * 4 + 0];
        o.y = acc[i][1] * ri * rn[64 + tx * 4 + 1];
        o.z = acc[i][2] * ri * rn[64 + tx * 4 + 2];
        o.w = acc[i][3] * ri * rn[64 + tx * 4 + 3];
        *(float4*)&ob[ii * TT + tx * 4] = o;
    }
}

// ---------------------------------------------------------------------------
extern "C" void kernel_launch(void* const* d_in, const int* in_sizes, int n_in,
                              void* d_out, int out_size)
{
    const float* e  = (const float*)d_in[0];   // [B,K,T]
    const float* f  = (const float*)d_in[1];   // [B,DF,N]
    const float* gp = (const float*)d_in[2];   // scalar gamma
    const float* W  = (const float*)d_in[3];   // [DF,K]
    const float* bs = (const float*)d_in[4];   // [K]
    float* out = (float*)d_out;                // [B,T,T]

    float *pv = nullptr, *ps = nullptr, *pc = nullptr;
    cudaGetSymbolAddress((void**)&pv, g_v);
    cudaGetSymbolAddress((void**)&ps, g_s);
    cudaGetSymbolAddress((void**)&pc, g_c);

    // 1) v = W^T f + b : per batch K x N, reduce DF
    gemm_tn<128, 64, 8, 4, true><<<dim3(NN / 64, KK / 128, BB), 256>>>(
        W, f, bs, pv, DFE, KK, NN, NN, 0L, (long)DFE * NN, (long)KK * NN);

    // 2) s = e^T v : per batch T x N, reduce K
    gemm_tn<64, 64, 4, 4, false><<<dim3(NN / 64, TT / 64, BB), 256>>>(
        e, pv, nullptr, ps, KK, TT, NN, NN, (long)KK * TT, (long)KK * NN,
        (long)TT * NN);

    // 3) alpha = softmax(gamma * s) over N (in place)
    softmax_k<<<BB * TT, 256>>>(ps, gp);

    // 4) c = v alpha^T : per batch K x T, reduce N
    gemm_nt_c<<<dim3(1, KK / 64, BB), 256>>>(pv, ps, pc);

    // 5) cos = (c^T e) / outer(|c|,|e|)
    finalize_k<<<BB, 256>>>(pc, e, out);
}

// round 7
// speedup vs baseline: 1.8480x; 1.8480x over previous
#include <cuda_runtime.h>
#include <cstdint>

// Shapes (fixed by the problem)
constexpr int BB = 64;    // batch
constexpr int KK = 256;   // feature dim K
constexpr int TT = 64;    // word tokens
constexpr int DFE = 768;  // image channels
constexpr int NN = 1024;  // regions

// Scratch (device globals: allocation-free contract)
__device__ float g_u[BB * DFE * TT];   // u = W e        [B,DF,T] 12.6 MB
__device__ float g_s[BB * TT * NN];    // s / alpha      [B,T,N]  16.8 MB
__device__ float g_g[BB * DFE * TT];   // g = f alpha^T  [B,DF,T] 12.6 MB
__device__ float g_c[BB * KK * TT];    // c              [B,K,T]   4.2 MB
__device__ float g_wt[KK * DFE];       // W^T            [K,DF]   768 KB

typedef unsigned long long u64;

// ---- packed f32x2 helpers (Blackwell FFMA2; exact fp32) -------------------
__device__ __forceinline__ u64 bcast2(float x) {
    u64 r; asm("mov.b64 %0, {%1, %1};" : "=l"(r) : "f"(x)); return r;
}
__device__ __forceinline__ void fma2(u64& c, u64 a, u64 b) {
    asm("fma.rn.f32x2 %0, %1, %2, %3;" : "=l"(c) : "l"(a), "l"(b), "l"(c));
}
__device__ __forceinline__ float2 u2f2(u64 v) {
    float2 f; asm("mov.b64 {%0, %1}, %2;" : "=f"(f.x), "=f"(f.y) : "l"(v)); return f;
}

// ---------------------------------------------------------------------------
// prep: W [DF,K] -> W^T [K,DF]  (one-shot, tiny)
// ---------------------------------------------------------------------------
__global__ void prep_wt(const float* __restrict__ W) {
    int idx = blockIdx.x * 256 + threadIdx.x;   // DF*K = 196608
    int d = idx >> 8, k = idx & 255;
    g_wt[k * DFE + d] = W[idx];
}

// ---------------------------------------------------------------------------
// TN GEMM: C[m][n] = sum_r A[r*lda + m] * B[r*ldb + n]  (+ bias[m])
// THREADS threads (16 in x), each thread RM x RN (RN=4). FFMA2 over m-pairs.
// ---------------------------------------------------------------------------
template <int TM, int TN_, int RM, int RN, int THREADS, bool BIAS>
__global__ __launch_bounds__(THREADS) void gemm_tn(
    const float* __restrict__ A, const float* __restrict__ B,
    const float* __restrict__ bias, float* __restrict__ C,
    int Ktot, int lda, int ldb, int ldc, long aB, long bB, long cB)
{
    static_assert(RN == 4 && (RM % 4) == 0, "layout");
    constexpr int KC = 16;
    __shared__ float As[KC][TM];
    __shared__ float Bs[KC][TN_];

    const int b  = blockIdx.z;
    const int m0 = blockIdx.y * TM;
    const int n0 = blockIdx.x * TN_;
    const float* Ab = A + (long)b * aB;
    const float* Bb = B + (long)b * bB;
    float* Cb = C + (long)b * cB;

    const int tid = threadIdx.x;
    const int tx = tid & 15, ty = tid >> 4;

    u64 acc[RM / 2][RN];
#pragma unroll
    for (int p = 0; p < RM / 2; p++)
#pragma unroll
        for (int j = 0; j < RN; j++) acc[p][j] = 0ull;

    constexpr int A4 = KC * TM / 4;
    constexpr int B4 = KC * TN_ / 4;

    for (int k0 = 0; k0 < Ktot; k0 += KC) {
#pragma unroll
        for (int l = 0; l < A4 / THREADS; l++) {
            int idx = tid + l * THREADS;
            int r = idx / (TM / 4), c = idx % (TM / 4);
            *(float4*)&As[r][c * 4] =
                *(const float4*)&Ab[(long)(k0 + r) * lda + m0 + c * 4];
        }
#pragma unroll
        for (int l = 0; l < B4 / THREADS; l++) {
            int idx = tid + l * THREADS;
            int r = idx / (TN_ / 4), c = idx % (TN_ / 4);
            *(float4*)&Bs[r][c * 4] =
                *(const float4*)&Bb[(long)(k0 + r) * ldb + n0 + c * 4];
        }
        __syncthreads();

#pragma unroll
        for (int kk = 0; kk < KC; kk++) {
            u64 a2[RM / 2];
#pragma unroll
            for (int q = 0; q < RM / 4; q++) {
                ulonglong2 t = *(const ulonglong2*)&As[kk][ty * RM + q * 4];
                a2[2 * q]     = t.x;
                a2[2 * q + 1] = t.y;
            }
            float4 bvf = *(const float4*)&Bs[kk][tx * RN];
            u64 b2[4] = {bcast2(bvf.x), bcast2(bvf.y), bcast2(bvf.z), bcast2(bvf.w)};
#pragma unroll
            for (int p = 0; p < RM / 2; p++)
#pragma unroll
                for (int j = 0; j < RN; j++) fma2(acc[p][j], a2[p], b2[j]);
        }
        __syncthreads();
    }

#pragma unroll
    for (int p = 0; p < RM / 2; p++) {
        int r0 = m0 + ty * RM + 2 * p;
        float bi0 = 0.f, bi1 = 0.f;
        if (BIAS) { bi0 = bias[r0]; bi1 = bias[r0 + 1]; }
        float2 f0 = u2f2(acc[p][0]);
        float2 f1 = u2f2(acc[p][1]);
        float2 f2 = u2f2(acc[p][2]);
        float2 f3 = u2f2(acc[p][3]);
        float4 o0 = make_float4(f0.x + bi0, f1.x + bi0, f2.x + bi0, f3.x + bi0);
        float4 o1 = make_float4(f0.y + bi1, f1.y + bi1, f2.y + bi1, f3.y + bi1);
        *(float4*)&Cb[(long)r0 * ldc + n0 + tx * RN]       = o0;
        *(float4*)&Cb[(long)(r0 + 1) * ldc + n0 + tx * RN] = o1;
    }
}

// ---------------------------------------------------------------------------
// Row softmax over N=1024 with gamma scaling (in place). 1 block per row.
// ---------------------------------------------------------------------------
__global__ __launch_bounds__(256) void softmax_k(float* __restrict__ S,
                                                 const float* __restrict__ gp)
{
    __shared__ float red[8];
    const long row = blockIdx.x;
    float* s = S + row * NN;
    const int tid = threadIdx.x;
    const float g = *gp;

    float4 v = *(const float4*)&s[tid * 4];
    v.x *= g; v.y *= g; v.z *= g; v.w *= g;

    float m = fmaxf(fmaxf(v.x, v.y), fmaxf(v.z, v.w));
#pragma unroll
    for (int o = 16; o > 0; o >>= 1) m = fmaxf(m, __shfl_xor_sync(0xffffffffu, m, o));
    if ((tid & 31) == 0) red[tid >> 5] = m;
    __syncthreads();
    m = red[0];
#pragma unroll
    for (int i = 1; i < 8; i++) m = fmaxf(m, red[i]);
    __syncthreads();

    float e0 = __expf(v.x - m), e1 = __expf(v.y - m);
    float e2 = __expf(v.z - m), e3 = __expf(v.w - m);
    float sum = (e0 + e1) + (e2 + e3);
#pragma unroll
    for (int o = 16; o > 0; o >>= 1) sum += __shfl_xor_sync(0xffffffffu, sum, o);
    if ((tid & 31) == 0) red[tid >> 5] = sum;
    __syncthreads();
    sum = ((red[0] + red[1]) + (red[2] + red[3])) +
          ((red[4] + red[5]) + (red[6] + red[7]));
    float r = 1.0f / sum;
    float4 o = make_float4(e0 * r, e1 * r, e2 * r, e3 * r);
    *(float4*)&s[tid * 4] = o;
}

// ---------------------------------------------------------------------------
// NT GEMM (f32x2 over n-pairs): g[b][d][t] = sum_n f[b][d][n] * alpha[b][t][n]
// CTA: 64 d-rows x 64 t-cols, reduce N=1024 in chunks of 32.
// Both operands are n-contiguous -> packed f32x2 on BOTH (no broadcast).
// ---------------------------------------------------------------------------
__global__ __launch_bounds__(256) void gemm_nt_g(const float* __restrict__ F,
                                                 const float* __restrict__ Al,
                                                 float* __restrict__ G)
{
    constexpr int PAD = 34;            // even row stride (8B-aligned float2)
    __shared__ float Fs[64][PAD];
    __shared__ float As[64][PAD];
    const int b  = blockIdx.z;
    const int m0 = blockIdx.y * 64;    // d tile
    const float* Fb = F + (long)b * DFE * NN + (long)m0 * NN;
    const float* Ab = Al + (long)b * TT * NN;
    const int tid = threadIdx.x;
    const int tx = tid & 15, ty = tid >> 4;

    u64 acc2[4][4];
#pragma unroll
    for (int i = 0; i < 4; i++)
#pragma unroll
        for (int j = 0; j < 4; j++) acc2[i][j] = 0ull;

    for (int n0 = 0; n0 < NN; n0 += 32) {
#pragma unroll
        for (int l = 0; l < 2; l++) {
            int idx = tid + l * 256;
            int r = idx >> 3, c = (idx & 7) * 4;
            float4 fv = *(const float4*)&Fb[(long)r * NN + n0 + c];
            float4 av = *(const float4*)&Ab[(long)r * NN + n0 + c];
            Fs[r][c] = fv.x; Fs[r][c + 1] = fv.y; Fs[r][c + 2] = fv.z; Fs[r][c + 3] = fv.w;
            As[r][c] = av.x; As[r][c + 1] = av.y; As[r][c + 2] = av.z; As[r][c + 3] = av.w;
        }
        __syncthreads();
#pragma unroll
        for (int nn = 0; nn < 16; nn++) {
            u64 av2[4], bv2[4];
#pragma unroll
            for (int i = 0; i < 4; i++)
                av2[i] = *(const u64*)&Fs[ty * 4 + i][nn * 2];
#pragma unroll
            for (int j = 0; j < 4; j++)
                bv2[j] = *(const u64*)&As[tx * 4 + j][nn * 2];
#pragma unroll
            for (int i = 0; i < 4; i++)
#pragma unroll
                for (int j = 0; j < 4; j++) fma2(acc2[i][j], av2[i], bv2[j]);
        }
        __syncthreads();
    }

    float* Gb = G + (long)b * DFE * TT + (long)m0 * TT;
#pragma unroll
    for (int i = 0; i < 4; i++) {
        float4 o;
        float2 p0 = u2f2(acc2[i][0]);
        float2 p1 = u2f2(acc2[i][1]);
        float2 p2 = u2f2(acc2[i][2]);
        float2 p3 = u2f2(acc2[i][3]);
        o.x = p0.x + p0.y; o.y = p1.x + p1.y; o.z = p2.x + p2.y; o.w = p3.x + p3.y;
        *(float4*)&Gb[(ty * 4 + i) * TT + tx * 4] = o;
    }
}

// ---------------------------------------------------------------------------
// Finalize: norms + cos[b][i][j] = (sum_k c[k][i] e[k][j]) / (lc[i] le[j])
// ---------------------------------------------------------------------------
__global__ __launch_bounds__(256) void finalize_k(const float* __restrict__ Cm,
                                                  const float* __restrict__ E,
                                                  float* __restrict__ Out)
{
    __shared__ float rn[128];
    __shared__ float As[16][64];
    __shared__ float Bs[16][64];
    const int b = blockIdx.x;
    const float* cb = Cm + (long)b * KK * TT;
    const float* eb = E + (long)b * KK * TT;
    const int tid = threadIdx.x;

    if (tid < 128) {
        const float* p = (tid < 64) ? cb : eb;
        int t = tid & 63;
        float ss = 0.f;
        for (int k = 0; k < KK; k++) {
            float x = p[k * TT + t];
            ss = fmaf(x, x, ss);
        }
        rn[tid] = rsqrtf(ss);
    }

    const int tx = tid & 15, ty = tid >> 4;
    float acc[4][4] = {};
    for (int k0 = 0; k0 < KK; k0 += 16) {
        *(float4*)&As[ty][tx * 4] = *(const float4*)&cb[(k0 + ty) * TT + tx * 4];
        *(float4*)&Bs[ty][tx * 4] = *(const float4*)&eb[(k0 + ty) * TT + tx * 4];
        __syncthreads();
#pragma unroll
        for (int kk = 0; kk < 16; kk++) {
            float4 a4 = *(const float4*)&As[kk][ty * 4];
            float4 b4 = *(const float4*)&Bs[kk][tx * 4];
            float av[4] = {a4.x, a4.y, a4.z, a4.w};
            float bv[4] = {b4.x, b4.y, b4.z, b4.w};
#pragma unroll
            for (int i = 0; i < 4; i++)
#pragma unroll
                for (int j = 0; j < 4; j++) acc[i][j] = fmaf(av[i], bv[j], acc[i][j]);
        }
        __syncthreads();
    }

    float* ob = Out + (long)b * TT * TT;
#pragma unroll
    for (int i = 0; i < 4; i++) {
        int ii = ty * 4 + i;
        float ri = rn[ii];
        float4 o;
        o.x = acc[i][0] * ri * rn[64 + tx * 4 + 0];
        o.y = acc[i][1] * ri * rn[64 + tx * 4 + 1];
        o.z = acc[i][2] * ri * rn[64 + tx * 4 + 2];
        o.w = acc[i][3] * ri * rn[64 + tx * 4 + 3];
        *(float4*)&ob[ii * TT + tx * 4] = o;
    }
}

// ---------------------------------------------------------------------------
extern "C" void kernel_launch(void* const* d_in, const int* in_sizes, int n_in,
                              void* d_out, int out_size)
{
    const float* e  = (const float*)d_in[0];   // [B,K,T]
    const float* f  = (const float*)d_in[1];   // [B,DF,N]
    const float* gp = (const float*)d_in[2];   // scalar gamma
    const float* W  = (const float*)d_in[3];   // [DF,K]
    const float* bs = (const float*)d_in[4];   // [K]
    float* out = (float*)d_out;                // [B,T,T]

    float *pu, *ps, *pg, *pc, *pwt;
    cudaGetSymbolAddress((void**)&pu, g_u);
    cudaGetSymbolAddress((void**)&ps, g_s);
    cudaGetSymbolAddress((void**)&pg, g_g);
    cudaGetSymbolAddress((void**)&pc, g_c);
    cudaGetSymbolAddress((void**)&pwt, g_wt);

    // 0) W^T  [K,DF]
    prep_wt<<<DFE * KK / 256, 256>>>(W);

    // 1) u = W e : per batch DF x T, reduce K.  (bias cancels in softmax)
    gemm_tn<128, 64, 8, 4, 256, false><<<dim3(1, DFE / 128, BB), 256>>>(
        pwt, e, nullptr, pu, KK, DFE, TT, TT, 0L, (long)KK * TT, (long)DFE * TT);

    // 2) s = u^T f : per batch T x N, reduce DF
    gemm_tn<64, 64, 8, 4, 128, false><<<dim3(NN / 64, TT / 64, BB), 128>>>(
        pu, f, nullptr, ps, DFE, TT, NN, NN, (long)DFE * TT, (long)DFE * NN,
        (long)TT * NN);

    // 3) alpha = softmax(gamma * s) over N (in place)
    softmax_k<<<BB * TT, 256>>>(ps, gp);

    // 4) g = f alpha^T : per batch DF x T, reduce N  (f32x2-paired NT)
    gemm_nt_g<<<dim3(1, DFE / 64, BB), 256>>>(f, ps, pg);

    // 5) c = W^T g + b : per batch K x T, reduce DF  (Sum_n alpha = 1)
    gemm_tn<128, 64, 8, 4, 256, true><<<dim3(1, KK / 128, BB), 256>>>(
        W, pg, bs, pc, DFE, KK, TT, TT, 0L, (long)DFE * TT, (long)KK * TT);

    // 6) cos = (c^T e) / outer(|c|,|e|)
    finalize_k<<<BB, 256>>>(pc, e, out);
}

// round 8
// speedup vs baseline: 2.3826x; 1.2893x over previous
#include <cuda_runtime.h>
#include <cstdint>

// Shapes (fixed by the problem)
constexpr int BB = 64;    // batch
constexpr int KK = 256;   // feature dim K
constexpr int TT = 64;    // word tokens
constexpr int DFE = 768;  // image channels
constexpr int NN = 1024;  // regions

// Scratch (device globals: allocation-free contract)
__device__ float g_u[BB * DFE * TT];   // u = W e        [B,DF,T]
__device__ float g_s[BB * TT * NN];    // s / alpha      [B,T,N]
__device__ float g_g[BB * DFE * TT];   // g = f alpha^T  [B,DF,T]
__device__ float g_c[BB * KK * TT];    // c              [B,K,T]
__device__ float g_wt[KK * DFE];       // W^T            [K,DF]

typedef unsigned long long u64;
typedef unsigned int u32;

// ---- packed f32x2 helpers (Blackwell FFMA2; exact fp32) -------------------
__device__ __forceinline__ u64 bcast2(float x) {
    u64 r; asm("mov.b64 %0, {%1, %1};" : "=l"(r) : "f"(x)); return r;
}
__device__ __forceinline__ void fma2(u64& c, u64 a, u64 b) {
    asm("fma.rn.f32x2 %0, %1, %2, %3;" : "=l"(c) : "l"(a), "l"(b), "l"(c));
}
__device__ __forceinline__ float2 u2f2(u64 v) {
    float2 f; asm("mov.b64 {%0, %1}, %2;" : "=f"(f.x), "=f"(f.y) : "l"(v)); return f;
}

// ---- cp.async helpers -----------------------------------------------------
__device__ __forceinline__ u32 smem_u32(const void* p) {
    u32 a;
    asm("{ .reg .u64 t; cvta.to.shared.u64 t, %1; cvt.u32.u64 %0, t; }"
        : "=r"(a) : "l"(p));
    return a;
}
__device__ __forceinline__ void cp16(u32 dst, const void* src) {
    asm volatile("cp.async.ca.shared.global [%0], [%1], 16;"
                 :: "r"(dst), "l"(src));
}
__device__ __forceinline__ void cp8(u32 dst, const void* src) {
    asm volatile("cp.async.ca.shared.global [%0], [%1], 8;"
                 :: "r"(dst), "l"(src));
}
#define CP_COMMIT() asm volatile("cp.async.commit_group;")
#define CP_WAIT1()  asm volatile("cp.async.wait_group 1;")
#define CP_WAIT0()  asm volatile("cp.async.wait_group 0;")

// ---------------------------------------------------------------------------
// prep: W [DF,K] -> W^T [K,DF]  (one-shot, tiny)
// ---------------------------------------------------------------------------
__global__ void prep_wt(const float* __restrict__ W) {
    int idx = blockIdx.x * 256 + threadIdx.x;   // DF*K = 196608
    int d = idx >> 8, k = idx & 255;
    g_wt[k * DFE + d] = W[idx];
}

// ---------------------------------------------------------------------------
// TN GEMM, cp.async double-buffered:
//   C[m][n] = sum_r A[r*lda + m] * B[r*ldb + n]  (+ bias[m])
// Thread layout: TX = TN_/RN columns of threads, TM/RM rows.
// ---------------------------------------------------------------------------
template <int TM, int TN_, int RM, int RN, int THREADS, bool BIAS>
__global__ __launch_bounds__(THREADS) void gemm_tn(
    const float* __restrict__ A, const float* __restrict__ B,
    const float* __restrict__ bias, float* __restrict__ C,
    int Ktot, int lda, int ldb, int ldc, long aB, long bB, long cB)
{
    static_assert(RN == 4 && (RM % 4) == 0, "layout");
    constexpr int KC = 16;
    constexpr int TX = TN_ / RN;
    static_assert((TM / RM) * TX == THREADS, "thread map");
    __shared__ float As[2][KC][TM];
    __shared__ float Bs[2][KC][TN_];

    const int b  = blockIdx.z;
    const int m0 = blockIdx.y * TM;
    const int n0 = blockIdx.x * TN_;
    const float* Ab = A + (long)b * aB;
    const float* Bb = B + (long)b * bB;
    float* Cb = C + (long)b * cB;

    const int tid = threadIdx.x;
    const int tx = tid % TX, ty = tid / TX;

    const u32 as0 = smem_u32(&As[0][0][0]);
    const u32 bs0 = smem_u32(&Bs[0][0][0]);
    constexpr int ASZ = KC * TM * 4;
    constexpr int BSZ = KC * TN_ * 4;

    u64 acc[RM / 2][RN];
#pragma unroll
    for (int p = 0; p < RM / 2; p++)
#pragma unroll
        for (int j = 0; j < RN; j++) acc[p][j] = 0ull;

    auto issue = [&](int st, int k0) {
#pragma unroll
        for (int l = 0; l < (KC * TM / 4) / THREADS; l++) {
            int idx = tid + l * THREADS;
            int r = idx / (TM / 4), c = idx % (TM / 4);
            cp16(as0 + st * ASZ + (r * TM + c * 4) * 4,
                 &Ab[(long)(k0 + r) * lda + m0 + c * 4]);
        }
#pragma unroll
        for (int l = 0; l < (KC * TN_ / 4) / THREADS; l++) {
            int idx = tid + l * THREADS;
            int r = idx / (TN_ / 4), c = idx % (TN_ / 4);
            cp16(bs0 + st * BSZ + (r * TN_ + c * 4) * 4,
                 &Bb[(long)(k0 + r) * ldb + n0 + c * 4]);
        }
        CP_COMMIT();
    };

    issue(0, 0);
    const int NCH = Ktot / KC;
    for (int ch = 0; ch < NCH; ch++) {
        if (ch + 1 < NCH) { issue((ch + 1) & 1, (ch + 1) * KC); CP_WAIT1(); }
        else              { CP_WAIT0(); }
        __syncthreads();
        const int st = ch & 1;
#pragma unroll
        for (int kk = 0; kk < KC; kk++) {
            u64 a2[RM / 2];
#pragma unroll
            for (int q = 0; q < RM / 4; q++) {
                ulonglong2 t = *(const ulonglong2*)&As[st][kk][ty * RM + q * 4];
                a2[2 * q]     = t.x;
                a2[2 * q + 1] = t.y;
            }
            float4 bvf = *(const float4*)&Bs[st][kk][tx * RN];
            u64 b2[4] = {bcast2(bvf.x), bcast2(bvf.y), bcast2(bvf.z), bcast2(bvf.w)};
#pragma unroll
            for (int p = 0; p < RM / 2; p++)
#pragma unroll
                for (int j = 0; j < RN; j++) fma2(acc[p][j], a2[p], b2[j]);
        }
        __syncthreads();
    }

#pragma unroll
    for (int p = 0; p < RM / 2; p++) {
        int r0 = m0 + ty * RM + 2 * p;
        float bi0 = 0.f, bi1 = 0.f;
        if (BIAS) { bi0 = bias[r0]; bi1 = bias[r0 + 1]; }
        float2 f0 = u2f2(acc[p][0]);
        float2 f1 = u2f2(acc[p][1]);
        float2 f2 = u2f2(acc[p][2]);
        float2 f3 = u2f2(acc[p][3]);
        float4 o0 = make_float4(f0.x + bi0, f1.x + bi0, f2.x + bi0, f3.x + bi0);
        float4 o1 = make_float4(f0.y + bi1, f1.y + bi1, f2.y + bi1, f3.y + bi1);
        *(float4*)&Cb[(long)r0 * ldc + n0 + tx * RN]       = o0;
        *(float4*)&Cb[(long)(r0 + 1) * ldc + n0 + tx * RN] = o1;
    }
}

// ---------------------------------------------------------------------------
// Row softmax over N=1024 with gamma scaling (in place). 1 block per row.
// ---------------------------------------------------------------------------
__global__ __launch_bounds__(256) void softmax_k(float* __restrict__ S,
                                                 const float* __restrict__ gp)
{
    __shared__ float red[8];
    const long row = blockIdx.x;
    float* s = S + row * NN;
    const int tid = threadIdx.x;
    const float g = *gp;

    float4 v = *(const float4*)&s[tid * 4];
    v.x *= g; v.y *= g; v.z *= g; v.w *= g;

    float m = fmaxf(fmaxf(v.x, v.y), fmaxf(v.z, v.w));
#pragma unroll
    for (int o = 16; o > 0; o >>= 1) m = fmaxf(m, __shfl_xor_sync(0xffffffffu, m, o));
    if ((tid & 31) == 0) red[tid >> 5] = m;
    __syncthreads();
    m = red[0];
#pragma unroll
    for (int i = 1; i < 8; i++) m = fmaxf(m, red[i]);
    __syncthreads();

    float e0 = __expf(v.x - m), e1 = __expf(v.y - m);
    float e2 = __expf(v.z - m), e3 = __expf(v.w - m);
    float sum = (e0 + e1) + (e2 + e3);
#pragma unroll
    for (int o = 16; o > 0; o >>= 1) sum += __shfl_xor_sync(0xffffffffu, sum, o);
    if ((tid & 31) == 0) red[tid >> 5] = sum;
    __syncthreads();
    sum = ((red[0] + red[1]) + (red[2] + red[3])) +
          ((red[4] + red[5]) + (red[6] + red[7]));
    float r = 1.0f / sum;
    float4 o = make_float4(e0 * r, e1 * r, e2 * r, e3 * r);
    *(float4*)&s[tid * 4] = o;
}

// ---------------------------------------------------------------------------
// NT GEMM (f32x2 over n-pairs, conflict-free, cp.async double-buffered):
//   g[b][d][t] = sum_n f[b][d][n] * alpha[b][t][n]
// CTA: 64 d-rows x 64 t-cols. Thread (tx,ty) 16x16 handles rows ty+16i,
// cols tx+16j -> smem reads hit all 16 8B bank-groups (pitch 34 floats).
// ---------------------------------------------------------------------------
__global__ __launch_bounds__(256) void gemm_nt_g(const float* __restrict__ F,
                                                 const float* __restrict__ Al,
                                                 float* __restrict__ G)
{
    constexpr int PAD = 34;            // 136B pitch: 8B aligned, 17 = 1 mod 16
    __shared__ float Fs[2][64][PAD];
    __shared__ float As[2][64][PAD];
    const int b  = blockIdx.z;
    const int m0 = blockIdx.y * 64;    // d tile
    const float* Fb = F + (long)b * DFE * NN + (long)m0 * NN;
    const float* Ab = Al + (long)b * TT * NN;
    const int tid = threadIdx.x;
    const int tx = tid & 15, ty = tid >> 4;

    const u32 fs0 = smem_u32(&Fs[0][0][0]);
    const u32 as0 = smem_u32(&As[0][0][0]);
    constexpr int SSZ = 64 * PAD * 4;

    u64 acc2[4][4];
#pragma unroll
    for (int i = 0; i < 4; i++)
#pragma unroll
        for (int j = 0; j < 4; j++) acc2[i][j] = 0ull;

    auto issue = [&](int st, int n0) {
#pragma unroll
        for (int l = 0; l < 2; l++) {
            int idx = tid + l * 256;
            int r = idx >> 3, c4 = (idx & 7) * 4;
            u32 off = (u32)(st * SSZ + (r * PAD + c4) * 4);
            const float* fsrc = &Fb[(long)r * NN + n0 + c4];
            const float* asrc = &Ab[(long)r * NN + n0 + c4];
            cp8(fs0 + off, fsrc);      cp8(fs0 + off + 8, fsrc + 2);
            cp8(as0 + off, asrc);      cp8(as0 + off + 8, asrc + 2);
        }
        CP_COMMIT();
    };

    issue(0, 0);
    const int NCH = NN / 32;
    for (int ch = 0; ch < NCH; ch++) {
        if (ch + 1 < NCH) { issue((ch + 1) & 1, (ch + 1) * 32); CP_WAIT1(); }
        else              { CP_WAIT0(); }
        __syncthreads();
        const int st = ch & 1;
#pragma unroll
        for (int nn = 0; nn < 16; nn++) {
            u64 av2[4], bv2[4];
#pragma unroll
            for (int i = 0; i < 4; i++)
                av2[i] = *(const u64*)&Fs[st][ty + 16 * i][nn * 2];
#pragma unroll
            for (int j = 0; j < 4; j++)
                bv2[j] = *(const u64*)&As[st][tx + 16 * j][nn * 2];
#pragma unroll
            for (int i = 0; i < 4; i++)
#pragma unroll
                for (int j = 0; j < 4; j++) fma2(acc2[i][j], av2[i], bv2[j]);
        }
        __syncthreads();
    }

    float* Gb = G + (long)b * DFE * TT + (long)m0 * TT;
#pragma unroll
    for (int i = 0; i < 4; i++)
#pragma unroll
        for (int j = 0; j < 4; j++) {
            float2 p = u2f2(acc2[i][j]);
            Gb[(ty + 16 * i) * TT + tx + 16 * j] = p.x + p.y;
        }
}

// ---------------------------------------------------------------------------
// Finalize: norms + cos[b][i][j] = (sum_k c[k][i] e[k][j]) / (lc[i] le[j])
// ---------------------------------------------------------------------------
__global__ __launch_bounds__(256) void finalize_k(const float* __restrict__ Cm,
                                                  const float* __restrict__ E,
                                                  float* __restrict__ Out)
{
    __shared__ float rn[128];
    __shared__ float As[16][64];
    __shared__ float Bs[16][64];
    const int b = blockIdx.x;
    const float* cb = Cm + (long)b * KK * TT;
    const float* eb = E + (long)b * KK * TT;
    const int tid = threadIdx.x;

    if (tid < 128) {
        const float* p = (tid < 64) ? cb : eb;
        int t = tid & 63;
        float ss = 0.f;
        for (int k = 0; k < KK; k++) {
            float x = p[k * TT + t];
            ss = fmaf(x, x, ss);
        }
        rn[tid] = rsqrtf(ss);
    }

    const int tx = tid & 15, ty = tid >> 4;
    float acc[4][4] = {};
    for (int k0 = 0; k0 < KK; k0 += 16) {
        *(float4*)&As[ty][tx * 4] = *(const float4*)&cb[(k0 + ty) * TT + tx * 4];
        *(float4*)&Bs[ty][tx * 4] = *(const float4*)&eb[(k0 + ty) * TT + tx * 4];
        __syncthreads();
#pragma unroll
        for (int kk = 0; kk < 16; kk++) {
            float4 a4 = *(const float4*)&As[kk][ty * 4];
            float4 b4 = *(const float4*)&Bs[kk][tx * 4];
            float av[4] = {a4.x, a4.y, a4.z, a4.w};
            float bv[4] = {b4.x, b4.y, b4.z, b4.w};
#pragma unroll
            for (int i = 0; i < 4; i++)
#pragma unroll
                for (int j = 0; j < 4; j++) acc[i][j] = fmaf(av[i], bv[j], acc[i][j]);
        }
        __syncthreads();
    }

    float* ob = Out + (long)b * TT * TT;
#pragma unroll
    for (int i = 0; i < 4; i++) {
        int ii = ty * 4 + i;
        float ri = rn[ii];
        float4 o;
        o.x = acc[i][0] * ri * rn[64 + tx * 4 + 0];
        o.y = acc[i][1] * ri * rn[64 + tx * 4 + 1];
        o.z = acc[i][2] * ri * rn[64 + tx * 4 + 2];
        o.w = acc[i][3] * ri * rn[64 + tx * 4 + 3];
        *(float4*)&ob[ii * TT + tx * 4] = o;
    }
}

// ---------------------------------------------------------------------------
extern "C" void kernel_launch(void* const* d_in, const int* in_sizes, int n_in,
                              void* d_out, int out_size)
{
    const float* e  = (const float*)d_in[0];   // [B,K,T]
    const float* f  = (const float*)d_in[1];   // [B,DF,N]
    const float* gp = (const float*)d_in[2];   // scalar gamma
    const float* W  = (const float*)d_in[3];   // [DF,K]
    const float* bs = (const float*)d_in[4];   // [K]
    float* out = (float*)d_out;                // [B,T,T]

    float *pu, *ps, *pg, *pc, *pwt;
    cudaGetSymbolAddress((void**)&pu, g_u);
    cudaGetSymbolAddress((void**)&ps, g_s);
    cudaGetSymbolAddress((void**)&pg, g_g);
    cudaGetSymbolAddress((void**)&pc, g_c);
    cudaGetSymbolAddress((void**)&pwt, g_wt);

    // 0) W^T  [K,DF]
    prep_wt<<<DFE * KK / 256, 256>>>(W);

    // 1) u = W e : per batch DF x T, reduce K.  (bias cancels in softmax)
    gemm_tn<128, 64, 8, 4, 256, false><<<dim3(1, DFE / 128, BB), 256>>>(
        pwt, e, nullptr, pu, KK, DFE, TT, TT, 0L, (long)KK * TT, (long)DFE * TT);

    // 2) s = u^T f : per batch T x N, reduce DF  (64x128 tiles)
    gemm_tn<64, 128, 8, 4, 256, false><<<dim3(NN / 128, 1, BB), 256>>>(
        pu, f, nullptr, ps, DFE, TT, NN, NN, (long)DFE * TT, (long)DFE * NN,
        (long)TT * NN);

    // 3) alpha = softmax(gamma * s) over N (in place)
    softmax_k<<<BB * TT, 256>>>(ps, gp);

    // 4) g = f alpha^T : per batch DF x T, reduce N (conflict-free f32x2 NT)
    gemm_nt_g<<<dim3(1, DFE / 64, BB), 256>>>(f, ps, pg);

    // 5) c = W^T g + b : per batch K x T, reduce DF  (Sum_n alpha = 1)
    gemm_tn<64, 64, 4, 4, 256, true><<<dim3(1, KK / 64, BB), 256>>>(
        W, pg, bs, pc, DFE, KK, TT, TT, 0L, (long)DFE * TT, (long)KK * TT);

    // 6) cos = (c^T e) / outer(|c|,|e|)
    finalize_k<<<BB, 256>>>(pc, e, out);
}

// round 9
// speedup vs baseline: 3.7164x; 1.5598x over previous
#include <cuda_runtime.h>
#include <cuda_bf16.h>
#include <cstdint>

// Shapes (fixed by the problem)
constexpr int BB = 64;    // batch
constexpr int KK = 256;   // feature dim K
constexpr int TT = 64;    // word tokens
constexpr int DFE = 768;  // image channels
constexpr int NN = 1024;  // regions

// Scratch (device globals: allocation-free contract)
__device__ float g_u[BB * TT * DFE];   // u' = (W e)^T   [B,T,DF]
__device__ float g_s[BB * TT * NN];    // s / alpha      [B,T,N]
__device__ float g_g[BB * DFE * TT];   // g = f alpha^T  [B,DF,T]
__device__ float g_c[BB * KK * TT];    // c              [B,K,T]
__device__ float g_wt[KK * DFE];       // W^T            [K,DF]

typedef unsigned long long u64;
typedef unsigned int u32;

// ---- packed f32x2 helpers (FFMA2; exact fp32 paths) -----------------------
__device__ __forceinline__ u64 bcast2(float x) {
    u64 r; asm("mov.b64 %0, {%1, %1};" : "=l"(r) : "f"(x)); return r;
}
__device__ __forceinline__ void fma2(u64& c, u64 a, u64 b) {
    asm("fma.rn.f32x2 %0, %1, %2, %3;" : "=l"(c) : "l"(a), "l"(b), "l"(c));
}
__device__ __forceinline__ float2 u2f2(u64 v) {
    float2 f; asm("mov.b64 {%0, %1}, %2;" : "=f"(f.x), "=f"(f.y) : "l"(v)); return f;
}

// ---- bf16 split + mma helpers ---------------------------------------------
__device__ __forceinline__ u32 smem_u32(const void* p) {
    u32 a;
    asm("{ .reg .u64 t; cvta.to.shared.u64 t, %1; cvt.u32.u64 %0, t; }"
        : "=r"(a) : "l"(p));
    return a;
}
// pack (lo_elem, hi_elem) -> bf16x2 (lo in low 16 bits)
__device__ __forceinline__ u32 pack_bf2(float a, float b) {
    u32 r; asm("cvt.rn.bf16x2.f32 %0, %1, %2;" : "=r"(r) : "f"(b), "f"(a));
    return r;
}
__device__ __forceinline__ float bflo(u32 p) { return __uint_as_float(p << 16); }
__device__ __forceinline__ float bfhi(u32 p) { return __uint_as_float(p & 0xffff0000u); }

__device__ __forceinline__ void split2(float2 x, u32& h2, u32& l2) {
    h2 = pack_bf2(x.x, x.y);
    l2 = pack_bf2(x.x - bflo(h2), x.y - bfhi(h2));
}

__device__ __forceinline__ void ldsm4(u32* r, u32 addr) {
    asm volatile("ldmatrix.sync.aligned.m8n8.x4.shared.b16 {%0,%1,%2,%3}, [%4];"
                 : "=r"(r[0]), "=r"(r[1]), "=r"(r[2]), "=r"(r[3]) : "r"(addr));
}
__device__ __forceinline__ void ldsm4t(u32* r, u32 addr) {
    asm volatile("ldmatrix.sync.aligned.m8n8.x4.trans.shared.b16 {%0,%1,%2,%3}, [%4];"
                 : "=r"(r[0]), "=r"(r[1]), "=r"(r[2]), "=r"(r[3]) : "r"(addr));
}
__device__ __forceinline__ void mma_bf16(float* d, const u32* a, const u32* b) {
    asm volatile(
        "mma.sync.aligned.m16n8k16.row.col.f32.bf16.bf16.f32 "
        "{%0,%1,%2,%3}, {%4,%5,%6,%7}, {%8,%9}, {%0,%1,%2,%3};"
        : "+f"(d[0]), "+f"(d[1]), "+f"(d[2]), "+f"(d[3])
        : "r"(a[0]), "r"(a[1]), "r"(a[2]), "r"(a[3]), "r"(b[0]), "r"(b[1]));
}

// ---------------------------------------------------------------------------
// prep: W [DF,K] -> W^T [K,DF]  (one-shot, tiny)
// ---------------------------------------------------------------------------
__global__ void prep_wt(const float* __restrict__ W) {
    int idx = blockIdx.x * 256 + threadIdx.x;   // DF*K
    int d = idx >> 8, k = idx & 255;
    g_wt[k * DFE + d] = W[idx];
}

// ---------------------------------------------------------------------------
// TN GEMM (exact fp32 FFMA2, cp.async-free simple double buffer kept out:
// these are the two small 0.8-GMAC GEMMs).
// C[m][n] = sum_r A[r*lda+m] * B[r*ldb+n] (+bias[m])
// ---------------------------------------------------------------------------
template <int TM, int TN_, int RM, int RN, int THREADS, bool BIAS>
__global__ __launch_bounds__(THREADS) void gemm_tn(
    const float* __restrict__ A, const float* __restrict__ B,
    const float* __restrict__ bias, float* __restrict__ C,
    int Ktot, int lda, int ldb, int ldc, long aB, long bB, long cB)
{
    static_assert(RN == 4 && (RM % 4) == 0, "layout");
    constexpr int KC = 16;
    constexpr int TX = TN_ / RN;
    static_assert((TM / RM) * TX == THREADS, "thread map");
    __shared__ float As[KC][TM];
    __shared__ float Bs[KC][TN_];

    const int b  = blockIdx.z;
    const int m0 = blockIdx.y * TM;
    const int n0 = blockIdx.x * TN_;
    const float* Ab = A + (long)b * aB;
    const float* Bb = B + (long)b * bB;
    float* Cb = C + (long)b * cB;

    const int tid = threadIdx.x;
    const int tx = tid % TX, ty = tid / TX;

    u64 acc[RM / 2][RN];
#pragma unroll
    for (int p = 0; p < RM / 2; p++)
#pragma unroll
        for (int j = 0; j < RN; j++) acc[p][j] = 0ull;

    for (int k0 = 0; k0 < Ktot; k0 += KC) {
#pragma unroll
        for (int l = 0; l < (KC * TM / 4) / THREADS; l++) {
            int idx = tid + l * THREADS;
            int r = idx / (TM / 4), c = idx % (TM / 4);
            *(float4*)&As[r][c * 4] =
                *(const float4*)&Ab[(long)(k0 + r) * lda + m0 + c * 4];
        }
#pragma unroll
        for (int l = 0; l < (KC * TN_ / 4) / THREADS; l++) {
            int idx = tid + l * THREADS;
            int r = idx / (TN_ / 4), c = idx % (TN_ / 4);
            *(float4*)&Bs[r][c * 4] =
                *(const float4*)&Bb[(long)(k0 + r) * ldb + n0 + c * 4];
        }
        __syncthreads();
#pragma unroll
        for (int kk = 0; kk < KC; kk++) {
            u64 a2[RM / 2];
#pragma unroll
            for (int q = 0; q < RM / 4; q++) {
                ulonglong2 t = *(const ulonglong2*)&As[kk][ty * RM + q * 4];
                a2[2 * q]     = t.x;
                a2[2 * q + 1] = t.y;
            }
            float4 bvf = *(const float4*)&Bs[kk][tx * RN];
            u64 b2[4] = {bcast2(bvf.x), bcast2(bvf.y), bcast2(bvf.z), bcast2(bvf.w)};
#pragma unroll
            for (int p = 0; p < RM / 2; p++)
#pragma unroll
                for (int j = 0; j < RN; j++) fma2(acc[p][j], a2[p], b2[j]);
        }
        __syncthreads();
    }

#pragma unroll
    for (int p = 0; p < RM / 2; p++) {
        int r0 = m0 + ty * RM + 2 * p;
        float bi0 = 0.f, bi1 = 0.f;
        if (BIAS) { bi0 = bias[r0]; bi1 = bias[r0 + 1]; }
        float2 f0 = u2f2(acc[p][0]);
        float2 f1 = u2f2(acc[p][1]);
        float2 f2 = u2f2(acc[p][2]);
        float2 f3 = u2f2(acc[p][3]);
        float4 o0 = make_float4(f0.x + bi0, f1.x + bi0, f2.x + bi0, f3.x + bi0);
        float4 o1 = make_float4(f0.y + bi1, f1.y + bi1, f2.y + bi1, f3.y + bi1);
        *(float4*)&Cb[(long)r0 * ldc + n0 + tx * RN]       = o0;
        *(float4*)&Cb[(long)(r0 + 1) * ldc + n0 + tx * RN] = o1;
    }
}

// ---------------------------------------------------------------------------
// s = u'^T f via mma.sync bf16, 3-term split (hi*hi + hi*lo + lo*hi).
// Per CTA: all T=64 rows x 64-region tile; k = DF in chunks of 32.
// A = u' [T][DF] (row-major k-contig, SW64 smem, ldmatrix non-trans)
// B = f  [DF][N] (k-major rows, SW128 smem, ldmatrix TRANS)
// ---------------------------------------------------------------------------
__global__ __launch_bounds__(256) void s_mma(const float* __restrict__ U,
                                             const float* __restrict__ F,
                                             float* __restrict__ S)
{
    __shared__ __align__(16) char sm[2][16384];
    // per stage: Ah [0,4K) Al [4K,8K) Bh [8K,12K) Bl [12K,16K)
    const int b  = blockIdx.z;
    const int n0 = blockIdx.x * 64;
    const float* Ub = U + (long)b * TT * DFE;
    const float* Fb = F + (long)b * DFE * NN;
    const int tid = threadIdx.x;
    const int warp = tid >> 5, l = tid & 31;
    const int wm = warp >> 2, wn = warp & 3;
    const u32 smb = smem_u32(sm);

    float2 ra[4], rb[4];
    float d[2][2][4];
#pragma unroll
    for (int i = 0; i < 2; i++)
#pragma unroll
        for (int j = 0; j < 2; j++)
#pragma unroll
            for (int q = 0; q < 4; q++) d[i][j][q] = 0.f;

    auto ldg = [&](int d0) {
#pragma unroll
        for (int it = 0; it < 4; it++) {
            int w = it * 256 + tid;
            int t = w >> 4, wd = w & 15;
            ra[it] = *(const float2*)&Ub[(long)t * DFE + d0 + wd * 2];
            int k = w >> 5, wd2 = w & 31;
            rb[it] = *(const float2*)&Fb[(long)(d0 + k) * NN + n0 + wd2 * 2];
        }
    };
    auto sts = [&](int st) {
        char* base = sm[st];
#pragma unroll
        for (int it = 0; it < 4; it++) {
            int w = it * 256 + tid;
            {   int t = w >> 4, wd = w & 15;
                u32 h2, l2; split2(ra[it], h2, l2);
                u32 off = t * 64 + (((wd >> 2) ^ ((t >> 1) & 3)) << 4) + (wd & 3) * 4;
                *(u32*)(base + off)        = h2;
                *(u32*)(base + 4096 + off) = l2; }
            {   int k = w >> 5, wd = w & 31;
                u32 h2, l2; split2(rb[it], h2, l2);
                u32 off = k * 128 + (((wd >> 2) ^ (k & 7)) << 4) + (wd & 3) * 4;
                *(u32*)(base + 8192  + off) = h2;
                *(u32*)(base + 12288 + off) = l2; }
        }
    };

    ldg(0);
    constexpr int NCH = DFE / 32;   // 24
    for (int ch = 0; ch < NCH; ch++) {
        const int st = ch & 1;
        sts(st);
        __syncthreads();
        if (ch + 1 < NCH) ldg((ch + 1) * 32);
        const u32 ab = smb + st * 16384;
        const u32 bb = ab + 8192;
#pragma unroll
        for (int kk = 0; kk < 2; kk++) {
            u32 Ah[2][4], Al[2][4], Bh[4], Bl[4];
            int rA = wm * 32 + (l & 7) + ((l >> 3) & 1) * 8;
            int cA = kk * 2 + (l >> 4);
#pragma unroll
            for (int mf = 0; mf < 2; mf++) {
                int r = rA + mf * 16;
                u32 off = r * 64 + ((cA ^ ((r >> 1) & 3)) << 4);
                ldsm4(Ah[mf], ab + off);
                ldsm4(Al[mf], ab + 4096 + off);
            }
            int rB = kk * 16 + (l & 7) + ((l >> 3) & 1) * 8;
            int cB = wn * 2 + (l >> 4);
            u32 offb = rB * 128 + ((cB ^ (rB & 7)) << 4);
            ldsm4t(Bh, bb + offb);
            ldsm4t(Bl, bb + 4096 + offb);
#pragma unroll
            for (int mf = 0; mf < 2; mf++)
#pragma unroll
                for (int nf = 0; nf < 2; nf++) {
                    mma_bf16(d[mf][nf], Ah[mf], &Bh[nf * 2]);
                    mma_bf16(d[mf][nf], Ah[mf], &Bl[nf * 2]);
                    mma_bf16(d[mf][nf], Al[mf], &Bh[nf * 2]);
                }
        }
        __syncthreads();
    }

    const int g = l >> 2, tig = l & 3;
#pragma unroll
    for (int mf = 0; mf < 2; mf++)
#pragma unroll
        for (int nf = 0; nf < 2; nf++) {
            int t = wm * 32 + mf * 16 + g;
            int n = n0 + wn * 16 + nf * 8 + tig * 2;
            float* p = &S[((long)b * TT + t) * NN + n];
            *(float2*)p            = make_float2(d[mf][nf][0], d[mf][nf][1]);
            *(float2*)(p + 8 * NN) = make_float2(d[mf][nf][2], d[mf][nf][3]);
        }
}

// ---------------------------------------------------------------------------
// Row softmax over N=1024 with gamma scaling (in place). 1 block per row.
// ---------------------------------------------------------------------------
__global__ __launch_bounds__(256) void softmax_k(float* __restrict__ S,
                                                 const float* __restrict__ gp)
{
    __shared__ float red[8];
    const long row = blockIdx.x;
    float* s = S + row * NN;
    const int tid = threadIdx.x;
    const float g = *gp;

    float4 v = *(const float4*)&s[tid * 4];
    v.x *= g; v.y *= g; v.z *= g; v.w *= g;

    float m = fmaxf(fmaxf(v.x, v.y), fmaxf(v.z, v.w));
#pragma unroll
    for (int o = 16; o > 0; o >>= 1) m = fmaxf(m, __shfl_xor_sync(0xffffffffu, m, o));
    if ((tid & 31) == 0) red[tid >> 5] = m;
    __syncthreads();
    m = red[0];
#pragma unroll
    for (int i = 1; i < 8; i++) m = fmaxf(m, red[i]);
    __syncthreads();

    float e0 = __expf(v.x - m), e1 = __expf(v.y - m);
    float e2 = __expf(v.z - m), e3 = __expf(v.w - m);
    float sum = (e0 + e1) + (e2 + e3);
#pragma unroll
    for (int o = 16; o > 0; o >>= 1) sum += __shfl_xor_sync(0xffffffffu, sum, o);
    if ((tid & 31) == 0) red[tid >> 5] = sum;
    __syncthreads();
    sum = ((red[0] + red[1]) + (red[2] + red[3])) +
          ((red[4] + red[5]) + (red[6] + red[7]));
    float r = 1.0f / sum;
    float4 o = make_float4(e0 * r, e1 * r, e2 * r, e3 * r);
    *(float4*)&s[tid * 4] = o;
}

// ---------------------------------------------------------------------------
// g = f alpha^T via mma.sync bf16 3-term split. k = n (regions).
// A = f [DF][N] (n-contig = k-contig rows, SW64), ldmatrix non-trans
// B = alpha [T][N] (k-contig rows, SW64), ldmatrix non-trans
// Output g [DF][T]. Per CTA: 64 d-rows x all T=64; 32 n-chunks.
// ---------------------------------------------------------------------------
__global__ __launch_bounds__(256) void g_mma(const float* __restrict__ F,
                                             const float* __restrict__ Al,
                                             float* __restrict__ G)
{
    __shared__ __align__(16) char sm[2][16384];
    // per stage: Ah [0,4K) Al [4K,8K) Bh [8K,12K) Bl [12K,16K)
    const int b  = blockIdx.z;
    const int d0 = blockIdx.x * 64;
    const float* Fb = F + ((long)b * DFE + d0) * NN;
    const float* Ab = Al + (long)b * TT * NN;
    const int tid = threadIdx.x;
    const int warp = tid >> 5, l = tid & 31;
    const int wm = warp >> 2, wn = warp & 3;
    const u32 smb = smem_u32(sm);

    float2 ra[4], rb[4];
    float d[2][2][4];
#pragma unroll
    for (int i = 0; i < 2; i++)
#pragma unroll
        for (int j = 0; j < 2; j++)
#pragma unroll
            for (int q = 0; q < 4; q++) d[i][j][q] = 0.f;

    auto ldg = [&](int n0) {
#pragma unroll
        for (int it = 0; it < 4; it++) {
            int w = it * 256 + tid;
            int r = w >> 4, wd = w & 15;
            ra[it] = *(const float2*)&Fb[(long)r * NN + n0 + wd * 2];
            rb[it] = *(const float2*)&Ab[(long)r * NN + n0 + wd * 2];
        }
    };
    auto sts = [&](int st) {
        char* base = sm[st];
#pragma unroll
        for (int it = 0; it < 4; it++) {
            int w = it * 256 + tid;
            int r = w >> 4, wd = w & 15;
            u32 off = r * 64 + (((wd >> 2) ^ ((r >> 1) & 3)) << 4) + (wd & 3) * 4;
            u32 h2, l2;
            split2(ra[it], h2, l2);
            *(u32*)(base + off)        = h2;
            *(u32*)(base + 4096 + off) = l2;
            split2(rb[it], h2, l2);
            *(u32*)(base + 8192  + off) = h2;
            *(u32*)(base + 12288 + off) = l2;
        }
    };

    ldg(0);
    constexpr int NCH = NN / 32;   // 32
    for (int ch = 0; ch < NCH; ch++) {
        const int st = ch & 1;
        sts(st);
        __syncthreads();
        if (ch + 1 < NCH) ldg((ch + 1) * 32);
        const u32 ab = smb + st * 16384;
        const u32 bb = ab + 8192;
#pragma unroll
        for (int kk = 0; kk < 2; kk++) {
            u32 Ah[2][4], Alo[2][4], Bh[4], Bl[4];
            int rA = wm * 32 + (l & 7) + ((l >> 3) & 1) * 8;
            int cA = kk * 2 + (l >> 4);
#pragma unroll
            for (int mf = 0; mf < 2; mf++) {
                int r = rA + mf * 16;
                u32 off = r * 64 + ((cA ^ ((r >> 1) & 3)) << 4);
                ldsm4(Ah[mf],  ab + off);
                ldsm4(Alo[mf], ab + 4096 + off);
            }
            int rB = wn * 16 + ((l >> 4) & 1) * 8 + (l & 7);
            int cB = kk * 2 + ((l >> 3) & 1);
            u32 offb = rB * 64 + ((cB ^ ((rB >> 1) & 3)) << 4);
            ldsm4(Bh, bb + offb);
            ldsm4(Bl, bb + 4096 + offb);
#pragma unroll
            for (int mf = 0; mf < 2; mf++)
#pragma unroll
                for (int nf = 0; nf < 2; nf++) {
                    mma_bf16(d[mf][nf], Ah[mf],  &Bh[nf * 2]);
                    mma_bf16(d[mf][nf], Ah[mf],  &Bl[nf * 2]);
                    mma_bf16(d[mf][nf], Alo[mf], &Bh[nf * 2]);
                }
        }
        __syncthreads();
    }

    const int g = l >> 2, tig = l & 3;
#pragma unroll
    for (int mf = 0; mf < 2; mf++)
#pragma unroll
        for (int nf = 0; nf < 2; nf++) {
            int dd = d0 + wm * 32 + mf * 16 + g;
            int t  = wn * 16 + nf * 8 + tig * 2;
            float* p = &G[((long)b * DFE + dd) * TT + t];
            *(float2*)p            = make_float2(d[mf][nf][0], d[mf][nf][1]);
            *(float2*)(p + 8 * TT) = make_float2(d[mf][nf][2], d[mf][nf][3]);
        }
}

// ---------------------------------------------------------------------------
// Finalize: norms + cos[b][i][j] = (sum_k c[k][i] e[k][j]) / (lc[i] le[j])
// ---------------------------------------------------------------------------
__global__ __launch_bounds__(256) void finalize_k(const float* __restrict__ Cm,
                                                  const float* __restrict__ E,
                                                  float* __restrict__ Out)
{
    __shared__ float rn[128];
    __shared__ float As[16][64];
    __shared__ float Bs[16][64];
    const int b = blockIdx.x;
    const float* cb = Cm + (long)b * KK * TT;
    const float* eb = E + (long)b * KK * TT;
    const int tid = threadIdx.x;

    if (tid < 128) {
        const float* p = (tid < 64) ? cb : eb;
        int t = tid & 63;
        float ss = 0.f;
        for (int k = 0; k < KK; k++) {
            float x = p[k * TT + t];
            ss = fmaf(x, x, ss);
        }
        rn[tid] = rsqrtf(ss);
    }

    const int tx = tid & 15, ty = tid >> 4;
    float acc[4][4] = {};
    for (int k0 = 0; k0 < KK; k0 += 16) {
        *(float4*)&As[ty][tx * 4] = *(const float4*)&cb[(k0 + ty) * TT + tx * 4];
        *(float4*)&Bs[ty][tx * 4] = *(const float4*)&eb[(k0 + ty) * TT + tx * 4];
        __syncthreads();
#pragma unroll
        for (int kk = 0; kk < 16; kk++) {
            float4 a4 = *(const float4*)&As[kk][ty * 4];
            float4 b4 = *(const float4*)&Bs[kk][tx * 4];
            float av[4] = {a4.x, a4.y, a4.z, a4.w};
            float bv[4] = {b4.x, b4.y, b4.z, b4.w};
#pragma unroll
            for (int i = 0; i < 4; i++)
#pragma unroll
                for (int j = 0; j < 4; j++) acc[i][j] = fmaf(av[i], bv[j], acc[i][j]);
        }
        __syncthreads();
    }

    float* ob = Out + (long)b * TT * TT;
#pragma unroll
    for (int i = 0; i < 4; i++) {
        int ii = ty * 4 + i;
        float ri = rn[ii];
        float4 o;
        o.x = acc[i][0] * ri * rn[64 + tx * 4 + 0];
        o.y = acc[i][1] * ri * rn[64 + tx * 4 + 1];
        o.z = acc[i][2] * ri * rn[64 + tx * 4 + 2];
        o.w = acc[i][3] * ri * rn[64 + tx * 4 + 3];
        *(float4*)&ob[ii * TT + tx * 4] = o;
    }
}

// ---------------------------------------------------------------------------
extern "C" void kernel_launch(void* const* d_in, const int* in_sizes, int n_in,
                              void* d_out, int out_size)
{
    const float* e  = (const float*)d_in[0];   // [B,K,T]
    const float* f  = (const float*)d_in[1];   // [B,DF,N]
    const float* gp = (const float*)d_in[2];   // scalar gamma
    const float* W  = (const float*)d_in[3];   // [DF,K]
    const float* bs = (const float*)d_in[4];   // [K]
    float* out = (float*)d_out;                // [B,T,T]

    float *pu, *ps, *pg, *pc, *pwt;
    cudaGetSymbolAddress((void**)&pu, g_u);
    cudaGetSymbolAddress((void**)&ps, g_s);
    cudaGetSymbolAddress((void**)&pg, g_g);
    cudaGetSymbolAddress((void**)&pc, g_c);
    cudaGetSymbolAddress((void**)&pwt, g_wt);

    // 0) W^T  [K,DF]
    prep_wt<<<DFE * KK / 256, 256>>>(W);

    // 1) u' = e^T W^T -> [B,T,DF]   (bias cancels in softmax)
    //    C[m=t][n=d] = sum_k e[k][t] * wt[k][d]
    gemm_tn<64, 128, 8, 4, 256, false><<<dim3(DFE / 128, 1, BB), 256>>>(
        e, pwt, nullptr, pu, KK, TT, DFE, DFE, (long)KK * TT, 0L,
        (long)TT * DFE);

    // 2) s = u' f  (bf16-split tensor cores): [B,T,N]
    s_mma<<<dim3(NN / 64, 1, BB), 256>>>(pu, f, ps);

    // 3) alpha = softmax(gamma * s) over N (in place)
    softmax_k<<<BB * TT, 256>>>(ps, gp);

    // 4) g = f alpha^T (bf16-split tensor cores): [B,DF,T]
    g_mma<<<dim3(DFE / 64, 1, BB), 256>>>(f, ps, pg);

    // 5) c = W^T g + b : per batch K x T, reduce DF  (Sum_n alpha = 1)
    gemm_tn<64, 64, 4, 4, 256, true><<<dim3(1, KK / 64, BB), 256>>>(
        W, pg, bs, pc, DFE, KK, TT, TT, 0L, (long)DFE * TT, (long)KK * TT);

    // 6) cos = (c^T e) / outer(|c|,|e|)
    finalize_k<<<BB, 256>>>(pc, e, out);
}

// round 10
// speedup vs baseline: 4.9004x; 1.3186x over previous
#include <cuda_runtime.h>
#include <cuda_bf16.h>
#include <cstdint>

// Shapes (fixed by the problem)
constexpr int BB = 64;    // batch
constexpr int KK = 256;   // feature dim K
constexpr int TT = 64;    // word tokens
constexpr int DFE = 768;  // image channels
constexpr int NN = 1024;  // regions

// Scratch (device globals: allocation-free contract)
__device__ float g_u[BB * TT * DFE];   // u' = (W e)^T   [B,T,DF]
__device__ float g_s[BB * TT * NN];    // s / alpha      [B,T,N]
__device__ float g_g[BB * DFE * TT];   // g = f alpha^T  [B,DF,T]
__device__ float g_c[BB * KK * TT];    // c              [B,K,T]
__device__ float g_wt[KK * DFE];       // W^T            [K,DF]

typedef unsigned int u32;

// ---- helpers --------------------------------------------------------------
__device__ __forceinline__ u32 smem_u32(const void* p) {
    u32 a;
    asm("{ .reg .u64 t; cvta.to.shared.u64 t, %1; cvt.u32.u64 %0, t; }"
        : "=r"(a) : "l"(p));
    return a;
}
// pack (a->low16, b->high16) bf16x2
__device__ __forceinline__ u32 pack_bf2(float a, float b) {
    u32 r; asm("cvt.rn.bf16x2.f32 %0, %1, %2;" : "=r"(r) : "f"(b), "f"(a));
    return r;
}
__device__ __forceinline__ float bflo(u32 p) { return __uint_as_float(p << 16); }
__device__ __forceinline__ float bfhi(u32 p) { return __uint_as_float(p & 0xffff0000u); }
__device__ __forceinline__ void split2(float2 x, u32& h2, u32& l2) {
    h2 = pack_bf2(x.x, x.y);
    l2 = pack_bf2(x.x - bflo(h2), x.y - bfhi(h2));
}
__device__ __forceinline__ void ldsm4(u32* r, u32 addr) {
    asm volatile("ldmatrix.sync.aligned.m8n8.x4.shared.b16 {%0,%1,%2,%3}, [%4];"
                 : "=r"(r[0]), "=r"(r[1]), "=r"(r[2]), "=r"(r[3]) : "r"(addr));
}
__device__ __forceinline__ void ldsm4t(u32* r, u32 addr) {
    asm volatile("ldmatrix.sync.aligned.m8n8.x4.trans.shared.b16 {%0,%1,%2,%3}, [%4];"
                 : "=r"(r[0]), "=r"(r[1]), "=r"(r[2]), "=r"(r[3]) : "r"(addr));
}
__device__ __forceinline__ void mma_bf16(float* d, const u32* a, const u32* b) {
    asm volatile(
        "mma.sync.aligned.m16n8k16.row.col.f32.bf16.bf16.f32 "
        "{%0,%1,%2,%3}, {%4,%5,%6,%7}, {%8,%9}, {%0,%1,%2,%3};"
        : "+f"(d[0]), "+f"(d[1]), "+f"(d[2]), "+f"(d[3])
        : "r"(a[0]), "r"(a[1]), "r"(a[2]), "r"(a[3]), "r"(b[0]), "r"(b[1]));
}

// Stage layout A8K+B4K kernels (u,c,g): Ah 0 | Al 8192 | Bh 16384 | Bl 20480
// Stage layout s_mma:                   Ah 0 | Al 4096 | Bh 8192(2x4K) | Bl 16384
constexpr int STG = 24576;

// ---------------------------------------------------------------------------
// prep: W [DF,K] -> W^T [K,DF]
// ---------------------------------------------------------------------------
__global__ void prep_wt(const float* __restrict__ W) {
    int idx = blockIdx.x * 256 + threadIdx.x;
    int d = idx >> 8, k = idx & 255;
    g_wt[k * DFE + d] = W[idx];
}

// ---------------------------------------------------------------------------
// u_mma: u[d][t] = sum_k W[d][k] e[k][t]; scatter-store transposed u'[t][d].
// CTA 128d x 64t, reduce K=256 in 8 chunks of 32. 3-term bf16 split.
// A = W (rows d, k-contig, SW64 non-trans); B = e (rows k, t-contig, SW128 trans)
// ---------------------------------------------------------------------------
__global__ __launch_bounds__(256) void u_mma(const float* __restrict__ W,
                                             const float* __restrict__ E,
                                             float* __restrict__ U)
{
    __shared__ __align__(16) char sm[2][STG];
    const int b = blockIdx.z;
    const int d0 = blockIdx.x * 128;
    const float* Eb = E + (long)b * KK * TT;
    const int tid = threadIdx.x;
    const int warp = tid >> 5, l = tid & 31;
    const int wm = warp >> 1, wn = warp & 1;
    const u32 smb = smem_u32(sm);

    float2 ra[8], rb[4];
    float acc[2][4][4] = {};

    auto ldg = [&](int k0) {
#pragma unroll
        for (int it = 0; it < 8; it++) {
            int w = it * 256 + tid; int r = w >> 4, wd = w & 15;
            ra[it] = *(const float2*)&W[(long)(d0 + r) * KK + k0 + wd * 2];
        }
#pragma unroll
        for (int it = 0; it < 4; it++) {
            int w = it * 256 + tid; int k = w >> 5, wd = w & 31;
            rb[it] = *(const float2*)&Eb[(long)(k0 + k) * TT + wd * 2];
        }
    };
    auto sts = [&](int st) {
        char* base = sm[st];
#pragma unroll
        for (int it = 0; it < 8; it++) {
            int w = it * 256 + tid; int r = w >> 4, wd = w & 15;
            u32 h2, l2; split2(ra[it], h2, l2);
            u32 off = r * 64 + (((wd >> 2) ^ ((r >> 1) & 3)) << 4) + (wd & 3) * 4;
            *(u32*)(base + off)        = h2;
            *(u32*)(base + 8192 + off) = l2;
        }
#pragma unroll
        for (int it = 0; it < 4; it++) {
            int w = it * 256 + tid; int k = w >> 5, wd = w & 31;
            u32 h2, l2; split2(rb[it], h2, l2);
            u32 off = k * 128 + (((wd >> 2) ^ (k & 7)) << 4) + (wd & 3) * 4;
            *(u32*)(base + 16384 + off) = h2;
            *(u32*)(base + 20480 + off) = l2;
        }
    };

    ldg(0);
    for (int ch = 0; ch < KK / 32; ch++) {
        int st = ch & 1;
        sts(st);
        __syncthreads();
        if (ch + 1 < KK / 32) ldg((ch + 1) * 32);
        u32 ab = smb + st * STG;
#pragma unroll
        for (int kk = 0; kk < 2; kk++) {
            u32 Ah[2][4], Alo[2][4], Bh[2][4], Bl[2][4];
#pragma unroll
            for (int mf = 0; mf < 2; mf++) {
                int r = wm * 32 + mf * 16 + (l & 7) + ((l >> 3) & 1) * 8;
                int cA = kk * 2 + (l >> 4);
                u32 off = r * 64 + ((cA ^ ((r >> 1) & 3)) << 4);
                ldsm4(Ah[mf],  ab + off);
                ldsm4(Alo[mf], ab + 8192 + off);
            }
            int rB = kk * 16 + (l & 7) + ((l >> 3) & 1) * 8;
#pragma unroll
            for (int nf2 = 0; nf2 < 2; nf2++) {
                int cB = wn * 4 + nf2 * 2 + (l >> 4);
                u32 offb = rB * 128 + ((cB ^ (rB & 7)) << 4);
                ldsm4t(Bh[nf2], ab + 16384 + offb);
                ldsm4t(Bl[nf2], ab + 20480 + offb);
            }
#pragma unroll
            for (int mf = 0; mf < 2; mf++)
#pragma unroll
                for (int nf = 0; nf < 4; nf++) {
                    int n2 = nf >> 1, j = nf & 1;
                    mma_bf16(acc[mf][nf], Ah[mf],  &Bh[n2][j * 2]);
                    mma_bf16(acc[mf][nf], Ah[mf],  &Bl[n2][j * 2]);
                    mma_bf16(acc[mf][nf], Alo[mf], &Bh[n2][j * 2]);
                }
        }
        __syncthreads();
    }

    const int g8 = l >> 2, tig = l & 3;
#pragma unroll
    for (int mf = 0; mf < 2; mf++)
#pragma unroll
        for (int nf = 0; nf < 4; nf++) {
            int m = wm * 32 + mf * 16 + g8;
            int t0 = wn * 32 + nf * 8 + tig * 2;
            float* p = &U[((long)b * TT + t0) * DFE + d0 + m];
            p[0]       = acc[mf][nf][0];
            p[DFE]     = acc[mf][nf][1];
            p[8]       = acc[mf][nf][2];
            p[DFE + 8] = acc[mf][nf][3];
        }
}

// ---------------------------------------------------------------------------
// s_mma: s[t][n] = sum_d u'[t][d] f[d][n].  CTA 64t x 128n, 24 chunks of 32.
// A = u' (SW64 non-trans); B = f (SW128 trans, two 64-n sub-tiles)
// ---------------------------------------------------------------------------
__global__ __launch_bounds__(256) void s_mma(const float* __restrict__ U,
                                             const float* __restrict__ F,
                                             float* __restrict__ S)
{
    __shared__ __align__(16) char sm[2][STG];
    const int b  = blockIdx.z;
    const int n0 = blockIdx.x * 128;
    const float* Ub = U + (long)b * TT * DFE;
    const float* Fb = F + (long)b * DFE * NN;
    const int tid = threadIdx.x;
    const int warp = tid >> 5, l = tid & 31;
    const int wm = warp >> 2, wn = warp & 3;
    const u32 smb = smem_u32(sm);

    float2 ra[4], rb[8];
    float acc[2][4][4] = {};

    auto ldg = [&](int dc) {
#pragma unroll
        for (int it = 0; it < 4; it++) {
            int w = it * 256 + tid; int r = w >> 4, wd = w & 15;
            ra[it] = *(const float2*)&Ub[(long)r * DFE + dc + wd * 2];
        }
#pragma unroll
        for (int it = 0; it < 8; it++) {
            int w = it * 256 + tid; int k = w >> 6, wd = w & 63;
            rb[it] = *(const float2*)&Fb[(long)(dc + k) * NN + n0 + wd * 2];
        }
    };
    auto sts = [&](int st) {
        char* base = sm[st];
#pragma unroll
        for (int it = 0; it < 4; it++) {
            int w = it * 256 + tid; int r = w >> 4, wd = w & 15;
            u32 h2, l2; split2(ra[it], h2, l2);
            u32 off = r * 64 + (((wd >> 2) ^ ((r >> 1) & 3)) << 4) + (wd & 3) * 4;
            *(u32*)(base + off)        = h2;
            *(u32*)(base + 4096 + off) = l2;
        }
#pragma unroll
        for (int it = 0; it < 8; it++) {
            int w = it * 256 + tid; int k = w >> 6, wd = w & 63;
            int sb = wd >> 5, wd32 = wd & 31;
            u32 h2, l2; split2(rb[it], h2, l2);
            u32 off = sb * 4096 + k * 128 +
                      (((wd32 >> 2) ^ (k & 7)) << 4) + (wd32 & 3) * 4;
            *(u32*)(base + 8192 + off)  = h2;
            *(u32*)(base + 16384 + off) = l2;
        }
    };

    ldg(0);
    for (int ch = 0; ch < DFE / 32; ch++) {
        int st = ch & 1;
        sts(st);
        __syncthreads();
        if (ch + 1 < DFE / 32) ldg((ch + 1) * 32);
        u32 ab = smb + st * STG;
        u32 bb = ab + 8192 + (wn >> 1) * 4096;   // warp's B sub-tile (hi part)
#pragma unroll
        for (int kk = 0; kk < 2; kk++) {
            u32 Ah[2][4], Alo[2][4], Bh[2][4], Bl[2][4];
#pragma unroll
            for (int mf = 0; mf < 2; mf++) {
                int r = wm * 32 + mf * 16 + (l & 7) + ((l >> 3) & 1) * 8;
                int cA = kk * 2 + (l >> 4);
                u32 off = r * 64 + ((cA ^ ((r >> 1) & 3)) << 4);
                ldsm4(Ah[mf],  ab + off);
                ldsm4(Alo[mf], ab + 4096 + off);
            }
            int rB = kk * 16 + (l & 7) + ((l >> 3) & 1) * 8;
#pragma unroll
            for (int nf2 = 0; nf2 < 2; nf2++) {
                int cB = (wn & 1) * 4 + nf2 * 2 + (l >> 4);
                u32 offb = rB * 128 + ((cB ^ (rB & 7)) << 4);
                ldsm4t(Bh[nf2], bb + offb);
                ldsm4t(Bl[nf2], bb + 8192 + offb);   // Bl region is +8192
            }
#pragma unroll
            for (int mf = 0; mf < 2; mf++)
#pragma unroll
                for (int nf = 0; nf < 4; nf++) {
                    int n2 = nf >> 1, j = nf & 1;
                    mma_bf16(acc[mf][nf], Ah[mf],  &Bh[n2][j * 2]);
                    mma_bf16(acc[mf][nf], Ah[mf],  &Bl[n2][j * 2]);
                    mma_bf16(acc[mf][nf], Alo[mf], &Bh[n2][j * 2]);
                }
        }
        __syncthreads();
    }

    const int g8 = l >> 2, tig = l & 3;
#pragma unroll
    for (int mf = 0; mf < 2; mf++)
#pragma unroll
        for (int nf = 0; nf < 4; nf++) {
            int t = wm * 32 + mf * 16 + g8;
            int n = n0 + wn * 32 + nf * 8 + tig * 2;
            float* p = &S[((long)b * TT + t) * NN + n];
            *(float2*)p            = make_float2(acc[mf][nf][0], acc[mf][nf][1]);
            *(float2*)(p + 8 * NN) = make_float2(acc[mf][nf][2], acc[mf][nf][3]);
        }
}

// ---------------------------------------------------------------------------
// Row softmax over N=1024 with gamma scaling (in place). 1 block per row.
// ---------------------------------------------------------------------------
__global__ __launch_bounds__(256) void softmax_k(float* __restrict__ S,
                                                 const float* __restrict__ gp)
{
    __shared__ float red[8];
    const long row = blockIdx.x;
    float* s = S + row * NN;
    const int tid = threadIdx.x;
    const float g = *gp;

    float4 v = *(const float4*)&s[tid * 4];
    v.x *= g; v.y *= g; v.z *= g; v.w *= g;

    float m = fmaxf(fmaxf(v.x, v.y), fmaxf(v.z, v.w));
#pragma unroll
    for (int o = 16; o > 0; o >>= 1) m = fmaxf(m, __shfl_xor_sync(0xffffffffu, m, o));
    if ((tid & 31) == 0) red[tid >> 5] = m;
    __syncthreads();
    m = red[0];
#pragma unroll
    for (int i = 1; i < 8; i++) m = fmaxf(m, red[i]);
    __syncthreads();

    float e0 = __expf(v.x - m), e1 = __expf(v.y - m);
    float e2 = __expf(v.z - m), e3 = __expf(v.w - m);
    float sum = (e0 + e1) + (e2 + e3);
#pragma unroll
    for (int o = 16; o > 0; o >>= 1) sum += __shfl_xor_sync(0xffffffffu, sum, o);
    if ((tid & 31) == 0) red[tid >> 5] = sum;
    __syncthreads();
    sum = ((red[0] + red[1]) + (red[2] + red[3])) +
          ((red[4] + red[5]) + (red[6] + red[7]));
    float r = 1.0f / sum;
    float4 o = make_float4(e0 * r, e1 * r, e2 * r, e3 * r);
    *(float4*)&s[tid * 4] = o;
}

// ---------------------------------------------------------------------------
// g_mma: g[d][t] = sum_n f[d][n] alpha[t][n].  CTA 128d x 64t, 32 chunks.
// A = f (SW64 non-trans, 128 rows); B = alpha (SW64 non-trans, 64 rows)
// ---------------------------------------------------------------------------
__global__ __launch_bounds__(256) void g_mma(const float* __restrict__ F,
                                             const float* __restrict__ Alp,
                                             float* __restrict__ G)
{
    __shared__ __align__(16) char sm[2][STG];
    const int b  = blockIdx.z;
    const int d0 = blockIdx.x * 128;
    const float* Fb = F + ((long)b * DFE + d0) * NN;
    const float* Ab = Alp + (long)b * TT * NN;
    const int tid = threadIdx.x;
    const int warp = tid >> 5, l = tid & 31;
    const int wm = warp >> 1, wn = warp & 1;
    const u32 smb = smem_u32(sm);

    float2 ra[8], rb[4];
    float acc[2][4][4] = {};

    auto ldg = [&](int nc) {
#pragma unroll
        for (int it = 0; it < 8; it++) {
            int w = it * 256 + tid; int r = w >> 4, wd = w & 15;
            ra[it] = *(const float2*)&Fb[(long)r * NN + nc + wd * 2];
        }
#pragma unroll
        for (int it = 0; it < 4; it++) {
            int w = it * 256 + tid; int r = w >> 4, wd = w & 15;
            rb[it] = *(const float2*)&Ab[(long)r * NN + nc + wd * 2];
        }
    };
    auto sts = [&](int st) {
        char* base = sm[st];
#pragma unroll
        for (int it = 0; it < 8; it++) {
            int w = it * 256 + tid; int r = w >> 4, wd = w & 15;
            u32 h2, l2; split2(ra[it], h2, l2);
            u32 off = r * 64 + (((wd >> 2) ^ ((r >> 1) & 3)) << 4) + (wd & 3) * 4;
            *(u32*)(base + off)        = h2;
            *(u32*)(base + 8192 + off) = l2;
        }
#pragma unroll
        for (int it = 0; it < 4; it++) {
            int w = it * 256 + tid; int r = w >> 4, wd = w & 15;
            u32 h2, l2; split2(rb[it], h2, l2);
            u32 off = r * 64 + (((wd >> 2) ^ ((r >> 1) & 3)) << 4) + (wd & 3) * 4;
            *(u32*)(base + 16384 + off) = h2;
            *(u32*)(base + 20480 + off) = l2;
        }
    };

    ldg(0);
    for (int ch = 0; ch < NN / 32; ch++) {
        int st = ch & 1;
        sts(st);
        __syncthreads();
        if (ch + 1 < NN / 32) ldg((ch + 1) * 32);
        u32 ab = smb + st * STG;
#pragma unroll
        for (int kk = 0; kk < 2; kk++) {
            u32 Ah[2][4], Alo[2][4], Bh[2][4], Bl[2][4];
#pragma unroll
            for (int mf = 0; mf < 2; mf++) {
                int r = wm * 32 + mf * 16 + (l & 7) + ((l >> 3) & 1) * 8;
                int cA = kk * 2 + (l >> 4);
                u32 off = r * 64 + ((cA ^ ((r >> 1) & 3)) << 4);
                ldsm4(Ah[mf],  ab + off);
                ldsm4(Alo[mf], ab + 8192 + off);
            }
#pragma unroll
            for (int nf2 = 0; nf2 < 2; nf2++) {
                int rB = wn * 32 + nf2 * 16 + ((l >> 4) & 1) * 8 + (l & 7);
                int cB = kk * 2 + ((l >> 3) & 1);
                u32 offb = rB * 64 + ((cB ^ ((rB >> 1) & 3)) << 4);
                ldsm4(Bh[nf2], ab + 16384 + offb);
                ldsm4(Bl[nf2], ab + 20480 + offb);
            }
#pragma unroll
            for (int mf = 0; mf < 2; mf++)
#pragma unroll
                for (int nf = 0; nf < 4; nf++) {
                    int n2 = nf >> 1, j = nf & 1;
                    mma_bf16(acc[mf][nf], Ah[mf],  &Bh[n2][j * 2]);
                    mma_bf16(acc[mf][nf], Ah[mf],  &Bl[n2][j * 2]);
                    mma_bf16(acc[mf][nf], Alo[mf], &Bh[n2][j * 2]);
                }
        }
        __syncthreads();
    }

    const int g8 = l >> 2, tig = l & 3;
#pragma unroll
    for (int mf = 0; mf < 2; mf++)
#pragma unroll
        for (int nf = 0; nf < 4; nf++) {
            int dd = d0 + wm * 32 + mf * 16 + g8;
            int t  = wn * 32 + nf * 8 + tig * 2;
            float* p = &G[((long)b * DFE + dd) * TT + t];
            *(float2*)p            = make_float2(acc[mf][nf][0], acc[mf][nf][1]);
            *(float2*)(p + 8 * TT) = make_float2(acc[mf][nf][2], acc[mf][nf][3]);
        }
}

// ---------------------------------------------------------------------------
// c_mma: c[m][t] = sum_d wt[m][d] g[d][t] + bias[m].  CTA 128m x 64t, 24 chunks.
// A = wt (SW64 non-trans); B = g (SW128 trans)
// ---------------------------------------------------------------------------
__global__ __launch_bounds__(256) void c_mma(const float* __restrict__ WT,
                                             const float* __restrict__ Gm,
                                             const float* __restrict__ bias,
                                             float* __restrict__ C)
{
    __shared__ __align__(16) char sm[2][STG];
    const int b  = blockIdx.z;
    const int m0 = blockIdx.x * 128;
    const float* Gb = Gm + (long)b * DFE * TT;
    const int tid = threadIdx.x;
    const int warp = tid >> 5, l = tid & 31;
    const int wm = warp >> 1, wn = warp & 1;
    const u32 smb = smem_u32(sm);

    float2 ra[8], rb[4];
    float acc[2][4][4] = {};

    auto ldg = [&](int dc) {
#pragma unroll
        for (int it = 0; it < 8; it++) {
            int w = it * 256 + tid; int r = w >> 4, wd = w & 15;
            ra[it] = *(const float2*)&WT[(long)(m0 + r) * DFE + dc + wd * 2];
        }
#pragma unroll
        for (int it = 0; it < 4; it++) {
            int w = it * 256 + tid; int k = w >> 5, wd = w & 31;
            rb[it] = *(const float2*)&Gb[(long)(dc + k) * TT + wd * 2];
        }
    };
    auto sts = [&](int st) {
        char* base = sm[st];
#pragma unroll
        for (int it = 0; it < 8; it++) {
            int w = it * 256 + tid; int r = w >> 4, wd = w & 15;
            u32 h2, l2; split2(ra[it], h2, l2);
            u32 off = r * 64 + (((wd >> 2) ^ ((r >> 1) & 3)) << 4) + (wd & 3) * 4;
            *(u32*)(base + off)        = h2;
            *(u32*)(base + 8192 + off) = l2;
        }
#pragma unroll
        for (int it = 0; it < 4; it++) {
            int w = it * 256 + tid; int k = w >> 5, wd = w & 31;
            u32 h2, l2; split2(rb[it], h2, l2);
            u32 off = k * 128 + (((wd >> 2) ^ (k & 7)) << 4) + (wd & 3) * 4;
            *(u32*)(base + 16384 + off) = h2;
            *(u32*)(base + 20480 + off) = l2;
        }
    };

    ldg(0);
    for (int ch = 0; ch < DFE / 32; ch++) {
        int st = ch & 1;
        sts(st);
        __syncthreads();
        if (ch + 1 < DFE / 32) ldg((ch + 1) * 32);
        u32 ab = smb + st * STG;
#pragma unroll
        for (int kk = 0; kk < 2; kk++) {
            u32 Ah[2][4], Alo[2][4], Bh[2][4], Bl[2][4];
#pragma unroll
            for (int mf = 0; mf < 2; mf++) {
                int r = wm * 32 + mf * 16 + (l & 7) + ((l >> 3) & 1) * 8;
                int cA = kk * 2 + (l >> 4);
                u32 off = r * 64 + ((cA ^ ((r >> 1) & 3)) << 4);
                ldsm4(Ah[mf],  ab + off);
                ldsm4(Alo[mf], ab + 8192 + off);
            }
            int rB = kk * 16 + (l & 7) + ((l >> 3) & 1) * 8;
#pragma unroll
            for (int nf2 = 0; nf2 < 2; nf2++) {
                int cB = wn * 4 + nf2 * 2 + (l >> 4);
                u32 offb = rB * 128 + ((cB ^ (rB & 7)) << 4);
                ldsm4t(Bh[nf2], ab + 16384 + offb);
                ldsm4t(Bl[nf2], ab + 20480 + offb);
            }
#pragma unroll
            for (int mf = 0; mf < 2; mf++)
#pragma unroll
                for (int nf = 0; nf < 4; nf++) {
                    int n2 = nf >> 1, j = nf & 1;
                    mma_bf16(acc[mf][nf], Ah[mf],  &Bh[n2][j * 2]);
                    mma_bf16(acc[mf][nf], Ah[mf],  &Bl[n2][j * 2]);
                    mma_bf16(acc[mf][nf], Alo[mf], &Bh[n2][j * 2]);
                }
        }
        __syncthreads();
    }

    const int g8 = l >> 2, tig = l & 3;
#pragma unroll
    for (int mf = 0; mf < 2; mf++) {
        int row = wm * 32 + mf * 16 + g8;
        float bi0 = bias[m0 + row], bi1 = bias[m0 + row + 8];
#pragma unroll
        for (int nf = 0; nf < 4; nf++) {
            int t0 = wn * 32 + nf * 8 + tig * 2;
            float* p = &C[((long)b * KK + m0 + row) * TT + t0];
            *(float2*)p = make_float2(acc[mf][nf][0] + bi0, acc[mf][nf][1] + bi0);
            *(float2*)(p + 8 * TT) =
                make_float2(acc[mf][nf][2] + bi1, acc[mf][nf][3] + bi1);
        }
    }
}

// ---------------------------------------------------------------------------
// Finalize: norms + cos[b][i][j] = (sum_k c[k][i] e[k][j]) / (lc[i] le[j])
// ---------------------------------------------------------------------------
__global__ __launch_bounds__(256) void finalize_k(const float* __restrict__ Cm,
                                                  const float* __restrict__ E,
                                                  float* __restrict__ Out)
{
    __shared__ float rn[128];
    __shared__ float As[16][64];
    __shared__ float Bs[16][64];
    const int b = blockIdx.x;
    const float* cb = Cm + (long)b * KK * TT;
    const float* eb = E + (long)b * KK * TT;
    const int tid = threadIdx.x;

    if (tid < 128) {
        const float* p = (tid < 64) ? cb : eb;
        int t = tid & 63;
        float ss = 0.f;
        for (int k = 0; k < KK; k++) {
            float x = p[k * TT + t];
            ss = fmaf(x, x, ss);
        }
        rn[tid] = rsqrtf(ss);
    }

    const int tx = tid & 15, ty = tid >> 4;
    float acc[4][4] = {};
    for (int k0 = 0; k0 < KK; k0 += 16) {
        *(float4*)&As[ty][tx * 4] = *(const float4*)&cb[(k0 + ty) * TT + tx * 4];
        *(float4*)&Bs[ty][tx * 4] = *(const float4*)&eb[(k0 + ty) * TT + tx * 4];
        __syncthreads();
#pragma unroll
        for (int kk = 0; kk < 16; kk++) {
            float4 a4 = *(const float4*)&As[kk][ty * 4];
            float4 b4 = *(const float4*)&Bs[kk][tx * 4];
            float av[4] = {a4.x, a4.y, a4.z, a4.w};
            float bv[4] = {b4.x, b4.y, b4.z, b4.w};
#pragma unroll
            for (int i = 0; i < 4; i++)
#pragma unroll
                for (int j = 0; j < 4; j++) acc[i][j] = fmaf(av[i], bv[j], acc[i][j]);
        }
        __syncthreads();
    }

    float* ob = Out + (long)b * TT * TT;
#pragma unroll
    for (int i = 0; i < 4; i++) {
        int ii = ty * 4 + i;
        float ri = rn[ii];
        float4 o;
        o.x = acc[i][0] * ri * rn[64 + tx * 4 + 0];
        o.y = acc[i][1] * ri * rn[64 + tx * 4 + 1];
        o.z = acc[i][2] * ri * rn[64 + tx * 4 + 2];
        o.w = acc[i][3] * ri * rn[64 + tx * 4 + 3];
        *(float4*)&ob[ii * TT + tx * 4] = o;
    }
}

// ---------------------------------------------------------------------------
extern "C" void kernel_launch(void* const* d_in, const int* in_sizes, int n_in,
                              void* d_out, int out_size)
{
    const float* e  = (const float*)d_in[0];   // [B,K,T]
    const float* f  = (const float*)d_in[1];   // [B,DF,N]
    const float* gp = (const float*)d_in[2];   // scalar gamma
    const float* W  = (const float*)d_in[3];   // [DF,K]
    const float* bs = (const float*)d_in[4];   // [K]
    float* out = (float*)d_out;                // [B,T,T]

    float *pu, *ps, *pg, *pc, *pwt;
    cudaGetSymbolAddress((void**)&pu, g_u);
    cudaGetSymbolAddress((void**)&ps, g_s);
    cudaGetSymbolAddress((void**)&pg, g_g);
    cudaGetSymbolAddress((void**)&pc, g_c);
    cudaGetSymbolAddress((void**)&pwt, g_wt);

    // 0) W^T (for c_mma A operand)
    prep_wt<<<DFE * KK / 256, 256>>>(W);

    // 1) u' = (W e)^T -> [B,T,DF]  (bias cancels in softmax)
    u_mma<<<dim3(DFE / 128, 1, BB), 256>>>(W, e, pu);

    // 2) s = u' f : [B,T,N]
    s_mma<<<dim3(NN / 128, 1, BB), 256>>>(pu, f, ps);

    // 3) alpha = softmax(gamma * s) over N (in place)
    softmax_k<<<BB * TT, 256>>>(ps, gp);

    // 4) g = f alpha^T : [B,DF,T]
    g_mma<<<dim3(DFE / 128, 1, BB), 256>>>(f, ps, pg);

    // 5) c = W^T g + b : [B,K,T]  (Sum_n alpha = 1)
    c_mma<<<dim3(KK / 128, 1, BB), 256>>>(pwt, pg, bs, pc);

    // 6) cos = (c^T e) / outer(|c|,|e|)
    finalize_k<<<BB, 256>>>(pc, e, out);
}